// round 1
// baseline (speedup 1.0000x reference)
#include <cuda_runtime.h>
#include <math.h>

#define NN   256      // total graph nodes
#define FDIM 1024
#define HIDD 512
#define NH   4
#define DD2  256
#define HD1  2048     // NH*HIDD
#define HD2  1024     // NH*DD2

// ---- device scratch (no allocations allowed) ----
__device__ float g_x  [NN * FDIM];
__device__ float g_xl1[NN * HD1];
__device__ float g_xr1[NN * HD1];
__device__ float g_o1 [NN * HD1];
__device__ float g_xl2[NN * HD2];
__device__ float g_xr2[NN * HD2];
__device__ float g_o2 [NN * HD2];
__device__ float g_y  [128 * FDIM];

// ---------------- concat inputs into x [256,1024] ----------------
__global__ void concat_kernel(const float* __restrict__ a, const float* __restrict__ b,
                              const float* __restrict__ c, const float* __restrict__ d) {
    int idx = blockIdx.x * blockDim.x + threadIdx.x;
    if (idx < 64 * FDIM) {
        g_x[idx]              = a[idx];
        g_x[64  * FDIM + idx] = b[idx];
        g_x[128 * FDIM + idx] = c[idx];
        g_x[192 * FDIM + idx] = d[idx];
    }
}

// ---------------- tiled fp32 GEMM: C = A[M,K] @ W[K,N] + bias[N] ----------------
// BM=BN=64, BK=16, 256 threads, 4x4 per thread. M,N,K all divisible here.
__global__ void gemm_bias(const float* __restrict__ A, const float* __restrict__ W,
                          const float* __restrict__ bias, float* __restrict__ C,
                          int M, int K, int N) {
    const int BM = 64, BN = 64, BK = 16, TM = 4, TN = 4;
    __shared__ float As[BK][BM];
    __shared__ float Ws[BK][BN];
    int brow = blockIdx.y * BM, bcol = blockIdx.x * BN;
    int tx = threadIdx.x % 16, ty = threadIdx.x / 16;
    float acc[TM][TN];
#pragma unroll
    for (int i = 0; i < TM; i++)
#pragma unroll
        for (int j = 0; j < TN; j++) acc[i][j] = 0.f;

    for (int k0 = 0; k0 < K; k0 += BK) {
        for (int idx = threadIdx.x; idx < BM * BK; idx += 256) {
            int m = idx / BK, kk = idx % BK;
            As[kk][m] = A[(brow + m) * K + k0 + kk];
        }
        for (int idx = threadIdx.x; idx < BK * BN; idx += 256) {
            int kk = idx / BN, n = idx % BN;
            Ws[kk][n] = W[(k0 + kk) * N + bcol + n];
        }
        __syncthreads();
#pragma unroll
        for (int kk = 0; kk < BK; kk++) {
            float av[TM], wv[TN];
#pragma unroll
            for (int i = 0; i < TM; i++) av[i] = As[kk][ty * TM + i];
#pragma unroll
            for (int j = 0; j < TN; j++) wv[j] = Ws[kk][tx * TN + j];
#pragma unroll
            for (int i = 0; i < TM; i++)
#pragma unroll
                for (int j = 0; j < TN; j++) acc[i][j] += av[i] * wv[j];
        }
        __syncthreads();
    }
#pragma unroll
    for (int i = 0; i < TM; i++) {
        int m = brow + ty * TM + i;
#pragma unroll
        for (int j = 0; j < TN; j++) {
            int n = bcol + tx * TN + j;
            C[m * N + n] = acc[i][j] + bias[n];
        }
    }
}

// ---------------- GATv2 attention: one block per (target i, head h) ----------------
// s[i,j] = sum_d att[h,d] * lrelu(xr[i,h,d] + xl[j,h,d]);  s[i,i] = -inf
// a = softmax_j(s);  out[i,h,d] = act( sum_j a_j * xl[j,h,d] + bias[h,d] )
// ACT: 0 = identity, 1 = ELU(alpha=1)
template <int D, int ACT>
__global__ void gatv2_attn(const float* __restrict__ xl, const float* __restrict__ xr,
                           const float* __restrict__ att, const float* __restrict__ bias,
                           float* __restrict__ out) {
    const int i   = blockIdx.x >> 2;
    const int h   = blockIdx.x & 3;
    const int tid = threadIdx.x;             // 256 threads
    const int lane = tid & 31, warp = tid >> 5;
    const int HD = NH * D;

    __shared__ float s_xr[D];
    __shared__ float s_att[D];
    __shared__ float s_a[NN];
    __shared__ float s_red[8];
    __shared__ float s_max, s_sum;

    for (int d = tid; d < D; d += 256) {
        s_xr[d]  = xr[i * HD + h * D + d];
        s_att[d] = att[h * D + d];
    }
    __syncthreads();

    // ---- scores: warp w handles j = w, w+8, ...
    for (int j = warp; j < NN; j += 8) {
        const float* xlj = xl + j * HD + h * D;
        float acc = 0.f;
        for (int d = lane; d < D; d += 32) {
            float z = s_xr[d] + xlj[d];
            float lr = z > 0.f ? z : 0.2f * z;
            acc += s_att[d] * lr;
        }
#pragma unroll
        for (int o = 16; o; o >>= 1) acc += __shfl_xor_sync(0xffffffffu, acc, o);
        if (lane == 0) s_a[j] = (j == i) ? -INFINITY : acc;
    }
    __syncthreads();

    // ---- softmax over 256 scores (one per thread)
    float v = s_a[tid];
    float m = v;
#pragma unroll
    for (int o = 16; o; o >>= 1) m = fmaxf(m, __shfl_xor_sync(0xffffffffu, m, o));
    if (lane == 0) s_red[warp] = m;
    __syncthreads();
    if (tid == 0) {
        float mm = s_red[0];
        for (int w = 1; w < 8; w++) mm = fmaxf(mm, s_red[w]);
        s_max = mm;
    }
    __syncthreads();
    float e = expf(v - s_max);
    float ss = e;
#pragma unroll
    for (int o = 16; o; o >>= 1) ss += __shfl_xor_sync(0xffffffffu, ss, o);
    if (lane == 0) s_red[warp] = ss;
    __syncthreads();
    if (tid == 0) {
        float t = 0.f;
        for (int w = 0; w < 8; w++) t += s_red[w];
        s_sum = t;
    }
    __syncthreads();
    s_a[tid] = e * (1.f / s_sum);
    __syncthreads();

    // ---- aggregate: out[i,h,d] = sum_j a_j * xl[j,h,d]
    for (int d = tid; d < D; d += 256) {
        float acc = 0.f;
        const float* xld = xl + h * D + d;
        for (int j = 0; j < NN; j++) acc += s_a[j] * xld[j * HD];
        acc += bias[h * D + d];
        if (ACT == 1) acc = acc > 0.f ? acc : expm1f(acc);
        out[i * HD + h * D + d] = acc;
    }
}

// ---------------- LayerNorm + ReLU + residual, rows 0..127 only ----------------
__global__ void ln_residual(const float* __restrict__ ln_g, const float* __restrict__ ln_b,
                            const float* __restrict__ rw, float* __restrict__ out) {
    const int i = blockIdx.x;                 // 0..127
    const int tid = threadIdx.x;              // 256
    const int lane = tid & 31, warp = tid >> 5;
    __shared__ float s_red1[8], s_red2[8];
    __shared__ float s_mu, s_rstd;

    const float* y = g_y + i * FDIM;
    float sum = 0.f, sq = 0.f;
    for (int c = tid; c < FDIM; c += 256) {
        float v = y[c];
        sum += v; sq += v * v;
    }
#pragma unroll
    for (int o = 16; o; o >>= 1) {
        sum += __shfl_xor_sync(0xffffffffu, sum, o);
        sq  += __shfl_xor_sync(0xffffffffu, sq,  o);
    }
    if (lane == 0) { s_red1[warp] = sum; s_red2[warp] = sq; }
    __syncthreads();
    if (tid == 0) {
        float ts = 0.f, tq = 0.f;
        for (int w = 0; w < 8; w++) { ts += s_red1[w]; tq += s_red2[w]; }
        float mu = ts / FDIM;
        float var = tq / FDIM - mu * mu;
        s_mu = mu;
        s_rstd = rsqrtf(var + 1e-5f);
    }
    __syncthreads();
    float mu = s_mu, rstd = s_rstd, w0 = rw[0];
    for (int c = tid; c < FDIM; c += 256) {
        float v = (y[c] - mu) * rstd * ln_g[c] + ln_b[c];
        v = fmaxf(v, 0.f);
        out[i * FDIM + c] = v + w0 * g_x[i * FDIM + c];
    }
}

// ---------------- launch ----------------
static inline void launch_gemm(const float* A, const float* W, const float* b, float* C,
                               int M, int K, int N) {
    dim3 grid(N / 64, M / 64);
    gemm_bias<<<grid, 256>>>(A, W, b, C, M, K, N);
}

extern "C" void kernel_launch(void* const* d_in, const int* in_sizes, int n_in,
                              void* d_out, int out_size) {
    (void)in_sizes; (void)n_in; (void)out_size;
    const float* v1f   = (const float*)d_in[0];
    const float* v2f   = (const float*)d_in[1];
    const float* v1fu  = (const float*)d_in[2];
    const float* v2fu  = (const float*)d_in[3];
    const float* Wl1   = (const float*)d_in[4];
    const float* bl1   = (const float*)d_in[5];
    const float* Wr1   = (const float*)d_in[6];
    const float* br1   = (const float*)d_in[7];
    const float* att1  = (const float*)d_in[8];
    const float* bias1 = (const float*)d_in[9];
    const float* Wl2   = (const float*)d_in[10];
    const float* bl2   = (const float*)d_in[11];
    const float* Wr2   = (const float*)d_in[12];
    const float* br2   = (const float*)d_in[13];
    const float* att2  = (const float*)d_in[14];
    const float* bias2 = (const float*)d_in[15];
    const float* Wout  = (const float*)d_in[16];
    const float* bout  = (const float*)d_in[17];
    const float* ln_g  = (const float*)d_in[18];
    const float* ln_b  = (const float*)d_in[19];
    const float* rw    = (const float*)d_in[20];
    float* out = (float*)d_out;

    float *x, *xl1, *xr1, *o1, *xl2, *xr2, *o2, *y;
    cudaGetSymbolAddress((void**)&x,   g_x);
    cudaGetSymbolAddress((void**)&xl1, g_xl1);
    cudaGetSymbolAddress((void**)&xr1, g_xr1);
    cudaGetSymbolAddress((void**)&o1,  g_o1);
    cudaGetSymbolAddress((void**)&xl2, g_xl2);
    cudaGetSymbolAddress((void**)&xr2, g_xr2);
    cudaGetSymbolAddress((void**)&o2,  g_o2);
    cudaGetSymbolAddress((void**)&y,   g_y);

    concat_kernel<<<(64 * FDIM + 255) / 256, 256>>>(v1f, v2f, v1fu, v2fu);

    launch_gemm(x, Wl1, bl1, xl1, NN, FDIM, HD1);
    launch_gemm(x, Wr1, br1, xr1, NN, FDIM, HD1);
    gatv2_attn<HIDD, 1><<<NN * NH, 256>>>(xl1, xr1, att1, bias1, o1);

    launch_gemm(o1, Wl2, bl2, xl2, NN, HD1, HD2);
    launch_gemm(o1, Wr2, br2, xr2, NN, HD1, HD2);
    gatv2_attn<DD2, 0><<<NN * NH, 256>>>(xl2, xr2, att2, bias2, o2);

    // only rows 0..127 reach the output
    launch_gemm(o2, Wout, bout, y, 128, FDIM, FDIM);
    ln_residual<<<128, 256>>>(ln_g, ln_b, rw, out);
}

// round 2
// speedup vs baseline: 2.2935x; 2.2935x over previous
#include <cuda_runtime.h>
#include <math.h>

#define NN   256      // total graph nodes
#define FDIM 1024
#define HIDD 512
#define NH   4
#define DD2  256
#define HD1  2048     // NH*HIDD
#define HD2  1024     // NH*DD2

// ---- device scratch (no allocations allowed) ----
__device__ float g_x  [NN * FDIM];
__device__ float g_xl1[NN * HD1];
__device__ float g_xr1[NN * HD1];
__device__ float g_o1 [NN * HD1];
__device__ float g_xl2[NN * HD2];
__device__ float g_xr2[NN * HD2];
__device__ float g_o2 [NN * HD2];
__device__ float g_y  [128 * FDIM];

// ---------------- concat inputs into x [256,1024] ----------------
__global__ void concat_kernel(const float* __restrict__ a, const float* __restrict__ b,
                              const float* __restrict__ c, const float* __restrict__ d) {
    int idx = blockIdx.x * blockDim.x + threadIdx.x;
    if (idx < 64 * FDIM) {
        g_x[idx]              = a[idx];
        g_x[64  * FDIM + idx] = b[idx];
        g_x[128 * FDIM + idx] = c[idx];
        g_x[192 * FDIM + idx] = d[idx];
    }
}

// ---------------- tiled fp32 dual-GEMM: C{z} = A @ W{z} + b{z} ----------------
// 256 threads. blockIdx.z selects (W,bias,C) so paired GEMMs fill the chip.
// Requires: (BM/TM)*(BN/TN)==256, BM*BK and BK*BN multiples of 1024, BK%4==0, BN%4==0.
template<int BM, int BN, int BK, int TM, int TN>
__global__ __launch_bounds__(256)
void gemm_bias2(const float* __restrict__ A,
                const float* __restrict__ W0, const float* __restrict__ W1,
                const float* __restrict__ b0, const float* __restrict__ b1,
                float* __restrict__ C0, float* __restrict__ C1,
                int M, int K, int N) {
    const float* W    = blockIdx.z ? W1 : W0;
    const float* bias = blockIdx.z ? b1 : b0;
    float*       C    = blockIdx.z ? C1 : C0;

    __shared__ float As[BK][BM];
    __shared__ float Ws[BK][BN];

    const int brow = blockIdx.y * BM;
    const int bcol = blockIdx.x * BN;
    const int tid  = threadIdx.x;
    const int tx   = tid % (BN / TN);
    const int ty   = tid / (BN / TN);

    float acc[TM][TN];
#pragma unroll
    for (int i = 0; i < TM; i++)
#pragma unroll
        for (int j = 0; j < TN; j++) acc[i][j] = 0.f;

    for (int k0 = 0; k0 < K; k0 += BK) {
        // A tile: BM x BK, float4 loads along K, transposed store
#pragma unroll
        for (int idx4 = tid * 4; idx4 < BM * BK; idx4 += 1024) {
            int m  = idx4 / BK;
            int kk = idx4 % BK;
            float4 a4 = *reinterpret_cast<const float4*>(&A[(brow + m) * K + k0 + kk]);
            As[kk + 0][m] = a4.x;
            As[kk + 1][m] = a4.y;
            As[kk + 2][m] = a4.z;
            As[kk + 3][m] = a4.w;
        }
        // W tile: BK x BN, float4 loads along N, direct store
#pragma unroll
        for (int idx4 = tid * 4; idx4 < BK * BN; idx4 += 1024) {
            int kk = idx4 / BN;
            int n  = idx4 % BN;
            float4 w4 = *reinterpret_cast<const float4*>(&W[(k0 + kk) * N + bcol + n]);
            *reinterpret_cast<float4*>(&Ws[kk][n]) = w4;
        }
        __syncthreads();
#pragma unroll
        for (int kk = 0; kk < BK; kk++) {
            float av[TM], wv[TN];
#pragma unroll
            for (int i = 0; i < TM; i++) av[i] = As[kk][ty * TM + i];
#pragma unroll
            for (int j = 0; j < TN; j++) wv[j] = Ws[kk][tx * TN + j];
#pragma unroll
            for (int i = 0; i < TM; i++)
#pragma unroll
                for (int j = 0; j < TN; j++) acc[i][j] = fmaf(av[i], wv[j], acc[i][j]);
        }
        __syncthreads();
    }
#pragma unroll
    for (int i = 0; i < TM; i++) {
        int m = brow + ty * TM + i;
#pragma unroll
        for (int j = 0; j < TN; j++) {
            int n = bcol + tx * TN + j;
            C[m * N + n] = acc[i][j] + bias[n];
        }
    }
}

// ---------------- GATv2 attention v2: one block = 8 targets x 1 head ----------------
// s[i,j] = sum_d att[h,d] * lrelu(xr[i,h,d] + xl[j,h,d]);  s[i,i] = -inf
// a = softmax_j(s);  out[i,h,d] = act( sum_j a_j * xl[j,h,d] + bias[h,d] )
template <int D, int ACT>
__global__ __launch_bounds__(256)
void gatv2_attn2(const float* __restrict__ xl, const float* __restrict__ xr,
                 const float* __restrict__ att, const float* __restrict__ bias,
                 float* __restrict__ out) {
    const int IT = 8;
    const int h    = blockIdx.x & 3;
    const int i0   = (blockIdx.x >> 2) * IT;
    const int tid  = threadIdx.x;
    const int lane = tid & 31, w = tid >> 5;
    const int HD   = NH * D;

    __shared__ float s_att[D];
    __shared__ float s_xr[IT][D];
    __shared__ float s_s[IT][NN];

    for (int d = tid; d < D; d += 256) s_att[d] = att[h * D + d];
    for (int idx = tid; idx < IT * D; idx += 256) {
        int it = idx / D, d = idx % D;
        s_xr[it][d] = xr[(i0 + it) * HD + h * D + d];
    }
    __syncthreads();

    // ---- scores: warp w handles sources j = w*32 .. w*32+31
    for (int t = 0; t < 32; t++) {
        int j = w * 32 + t;
        const float* xlj = xl + j * HD + h * D;
        float acc[IT];
#pragma unroll
        for (int it = 0; it < IT; it++) acc[it] = 0.f;
        for (int k = lane; k < D; k += 32) {
            float xlv   = __ldg(xlj + k);
            float attv  = s_att[k];
            float attv2 = 0.2f * attv;
#pragma unroll
            for (int it = 0; it < IT; it++) {
                float z = s_xr[it][k] + xlv;
                float c = (z > 0.f) ? attv : attv2;   // att * lrelu(z) == c * z
                acc[it] = fmaf(c, z, acc[it]);
            }
        }
#pragma unroll
        for (int it = 0; it < IT; it++) {
            float v = acc[it];
#pragma unroll
            for (int o = 16; o; o >>= 1) v += __shfl_xor_sync(0xffffffffu, v, o);
            acc[it] = v;
        }
        if (lane == 0) {
#pragma unroll
            for (int it = 0; it < IT; it++)
                s_s[it][j] = (j == i0 + it) ? -INFINITY : acc[it];
        }
    }
    __syncthreads();

    // ---- softmax: warp w normalizes target w's row (IT == 8 warps)
    {
        float v[8];
#pragma unroll
        for (int q = 0; q < 8; q++) v[q] = s_s[w][lane + 32 * q];
        float m = v[0];
#pragma unroll
        for (int q = 1; q < 8; q++) m = fmaxf(m, v[q]);
#pragma unroll
        for (int o = 16; o; o >>= 1) m = fmaxf(m, __shfl_xor_sync(0xffffffffu, m, o));
        float s = 0.f;
#pragma unroll
        for (int q = 0; q < 8; q++) { v[q] = expf(v[q] - m); s += v[q]; }
#pragma unroll
        for (int o = 16; o; o >>= 1) s += __shfl_xor_sync(0xffffffffu, s, o);
        float inv = 1.f / s;
#pragma unroll
        for (int q = 0; q < 8; q++) s_s[w][lane + 32 * q] = v[q] * inv;
    }
    __syncthreads();

    // ---- aggregate: thread handles one d (coalesced over threads), 8 targets in regs
    for (int d0 = 0; d0 < D; d0 += 256) {
        int d = d0 + tid;
        float acc[IT];
#pragma unroll
        for (int it = 0; it < IT; it++) acc[it] = 0.f;
        const float* xp = xl + h * D + d;
        for (int j = 0; j < NN; j++) {
            float xv = __ldg(xp + j * HD);
#pragma unroll
            for (int it = 0; it < IT; it++)
                acc[it] = fmaf(s_s[it][j], xv, acc[it]);
        }
        float bv = bias[h * D + d];
#pragma unroll
        for (int it = 0; it < IT; it++) {
            float o_ = acc[it] + bv;
            if (ACT == 1) o_ = o_ > 0.f ? o_ : expm1f(o_);
            out[(i0 + it) * HD + h * D + d] = o_;
        }
    }
}

// ---------------- LayerNorm + ReLU + residual, rows 0..127 only ----------------
__global__ __launch_bounds__(256)
void ln_residual(const float* __restrict__ ln_g, const float* __restrict__ ln_b,
                 const float* __restrict__ rw, float* __restrict__ out) {
    const int i = blockIdx.x;                 // 0..127
    const int tid = threadIdx.x;              // 256
    const int lane = tid & 31, warp = tid >> 5;
    __shared__ float s_red1[8], s_red2[8];
    __shared__ float s_mu, s_rstd;

    const float* y = g_y + i * FDIM;
    float sum = 0.f, sq = 0.f;
    for (int c = tid; c < FDIM; c += 256) {
        float v = y[c];
        sum += v; sq += v * v;
    }
#pragma unroll
    for (int o = 16; o; o >>= 1) {
        sum += __shfl_xor_sync(0xffffffffu, sum, o);
        sq  += __shfl_xor_sync(0xffffffffu, sq,  o);
    }
    if (lane == 0) { s_red1[warp] = sum; s_red2[warp] = sq; }
    __syncthreads();
    if (tid == 0) {
        float ts = 0.f, tq = 0.f;
        for (int w = 0; w < 8; w++) { ts += s_red1[w]; tq += s_red2[w]; }
        float mu = ts / FDIM;
        float var = tq / FDIM - mu * mu;
        s_mu = mu;
        s_rstd = rsqrtf(var + 1e-5f);
    }
    __syncthreads();
    float mu = s_mu, rstd = s_rstd, w0 = rw[0];
    for (int c = tid; c < FDIM; c += 256) {
        float v = (y[c] - mu) * rstd * ln_g[c] + ln_b[c];
        v = fmaxf(v, 0.f);
        out[i * FDIM + c] = v + w0 * g_x[i * FDIM + c];
    }
}

// ---------------- launch ----------------
extern "C" void kernel_launch(void* const* d_in, const int* in_sizes, int n_in,
                              void* d_out, int out_size) {
    (void)in_sizes; (void)n_in; (void)out_size;
    const float* v1f   = (const float*)d_in[0];
    const float* v2f   = (const float*)d_in[1];
    const float* v1fu  = (const float*)d_in[2];
    const float* v2fu  = (const float*)d_in[3];
    const float* Wl1   = (const float*)d_in[4];
    const float* bl1   = (const float*)d_in[5];
    const float* Wr1   = (const float*)d_in[6];
    const float* br1   = (const float*)d_in[7];
    const float* att1  = (const float*)d_in[8];
    const float* bias1 = (const float*)d_in[9];
    const float* Wl2   = (const float*)d_in[10];
    const float* bl2   = (const float*)d_in[11];
    const float* Wr2   = (const float*)d_in[12];
    const float* br2   = (const float*)d_in[13];
    const float* att2  = (const float*)d_in[14];
    const float* bias2 = (const float*)d_in[15];
    const float* Wout  = (const float*)d_in[16];
    const float* bout  = (const float*)d_in[17];
    const float* ln_g  = (const float*)d_in[18];
    const float* ln_b  = (const float*)d_in[19];
    const float* rw    = (const float*)d_in[20];
    float* out = (float*)d_out;

    float *x, *xl1, *xr1, *o1, *xl2, *xr2, *o2, *y;
    cudaGetSymbolAddress((void**)&x,   g_x);
    cudaGetSymbolAddress((void**)&xl1, g_xl1);
    cudaGetSymbolAddress((void**)&xr1, g_xr1);
    cudaGetSymbolAddress((void**)&o1,  g_o1);
    cudaGetSymbolAddress((void**)&xl2, g_xl2);
    cudaGetSymbolAddress((void**)&xr2, g_xr2);
    cudaGetSymbolAddress((void**)&o2,  g_o2);
    cudaGetSymbolAddress((void**)&y,   g_y);

    concat_kernel<<<(64 * FDIM + 255) / 256, 256>>>(v1f, v2f, v1fu, v2fu);

    // GAT layer 1: x[256,1024] @ {Wl1,Wr1}[1024,2048]  -> 128 CTAs (z fuses pair)
    {
        dim3 grid(HD1 / 128, NN / 64, 2);
        gemm_bias2<64, 128, 16, 4, 8><<<grid, 256>>>(x, Wl1, Wr1, bl1, br1, xl1, xr1,
                                                     NN, FDIM, HD1);
    }
    gatv2_attn2<HIDD, 1><<<(NN / 8) * NH, 256>>>(xl1, xr1, att1, bias1, o1);

    // GAT layer 2: o1[256,2048] @ {Wl2,Wr2}[2048,1024]  -> 128 CTAs
    {
        dim3 grid(HD2 / 64, NN / 64, 2);
        gemm_bias2<64, 64, 16, 4, 4><<<grid, 256>>>(o1, Wl2, Wr2, bl2, br2, xl2, xr2,
                                                    NN, HD1, HD2);
    }
    gatv2_attn2<DD2, 0><<<(NN / 8) * NH, 256>>>(xl2, xr2, att2, bias2, o2);

    // Output projection: only rows 0..127 reach the output. 64 CTAs.
    {
        dim3 grid(FDIM / 64, 128 / 32, 1);
        gemm_bias2<32, 64, 32, 2, 4><<<grid, 256>>>(o2, Wout, Wout, bout, bout, y, y,
                                                    128, FDIM, FDIM);
    }
    ln_residual<<<128, 256>>>(ln_g, ln_b, rw, out);
}

// round 3
// speedup vs baseline: 2.9726x; 1.2961x over previous
#include <cuda_runtime.h>
#include <math.h>

#define NN   256      // total graph nodes
#define FDIM 1024
#define HIDD 512
#define NH   4
#define DD2  256
#define HD1  2048     // NH*HIDD
#define HD2  1024     // NH*DD2

// ---- device scratch (no allocations allowed) ----
__device__ float g_x  [NN * FDIM];
__device__ float g_xl1[NN * HD1];
__device__ float g_xr1[NN * HD1];
__device__ float g_o1 [NN * HD1];
__device__ float g_xl2[NN * HD2];
__device__ float g_xr2[NN * HD2];
__device__ float g_o2 [NN * HD2];
__device__ float g_part[1 << 20];   // 4 MB split-K partials

// ---------------- concat inputs into x [256,1024] ----------------
__global__ void concat_kernel(const float* __restrict__ a, const float* __restrict__ b,
                              const float* __restrict__ c, const float* __restrict__ d) {
    int idx = blockIdx.x * blockDim.x + threadIdx.x;
    if (idx < 64 * FDIM) {
        g_x[idx]              = a[idx];
        g_x[64  * FDIM + idx] = b[idx];
        g_x[128 * FDIM + idx] = c[idx];
        g_x[192 * FDIM + idx] = d[idx];
    }
}

// ---------------- pipelined fp32 GEMM, 64x64 tile, BK=32, split-K, dual-GEMM ----
// z = gemm_idx * splitk + split. If splitk==1 writes C{g} with bias, else writes
// partial to g_part + z*M*N (bias added in the reduction).
__global__ __launch_bounds__(256)
void gemm_pipe(const float* __restrict__ A,
               const float* __restrict__ W0, const float* __restrict__ W1,
               const float* __restrict__ b0, const float* __restrict__ b1,
               float* __restrict__ C0, float* __restrict__ C1,
               int M, int K, int N, int splitk) {
    const int z = blockIdx.z;
    const int g = z / splitk;
    const int s = z % splitk;
    const float* W = g ? W1 : W0;
    const int kspan = K / splitk;
    const int kbeg  = s * kspan;
    const int nIters = kspan / 32;

    __shared__ float As[2][64][36];   // m-major, padded row (36 floats, 16B-aligned)
    __shared__ float Ws[2][32][64];   // k-major rows

    const int brow = blockIdx.y * 64;
    const int bcol = blockIdx.x * 64;
    const int tid  = threadIdx.x;
    const int tx   = tid & 15;        // 16 cols of threads (4 floats each)
    const int ty   = tid >> 4;        // 16 rows of threads (4 rows each)

    // global load coordinates (2 float4 per thread for each of A and W)
    const int aIdx0 = tid * 4;              // over 64*32 = 2048
    const int aIdx1 = aIdx0 + 1024;
    const int am0 = aIdx0 >> 5, ak0 = aIdx0 & 31;
    const int am1 = aIdx1 >> 5, ak1 = aIdx1 & 31;
    const int wIdx0 = tid * 4;              // over 32*64 = 2048
    const int wIdx1 = wIdx0 + 1024;
    const int wk0 = wIdx0 >> 6, wn0 = wIdx0 & 63;
    const int wk1 = wIdx1 >> 6, wn1 = wIdx1 & 63;

    const float* Ap0 = A + (size_t)(brow + am0) * K + kbeg + ak0;
    const float* Ap1 = A + (size_t)(brow + am1) * K + kbeg + ak1;
    const float* Wp0 = W + (size_t)(kbeg + wk0) * N + bcol + wn0;
    const float* Wp1 = W + (size_t)(kbeg + wk1) * N + bcol + wn1;

    float acc[4][4];
#pragma unroll
    for (int i = 0; i < 4; i++)
#pragma unroll
        for (int j = 0; j < 4; j++) acc[i][j] = 0.f;

    // ---- preload tile 0 into buffer 0
    {
        float4 ra0 = *reinterpret_cast<const float4*>(Ap0);
        float4 ra1 = *reinterpret_cast<const float4*>(Ap1);
        float4 rw0 = *reinterpret_cast<const float4*>(Wp0);
        float4 rw1 = *reinterpret_cast<const float4*>(Wp1);
        *reinterpret_cast<float4*>(&As[0][am0][ak0]) = ra0;
        *reinterpret_cast<float4*>(&As[0][am1][ak1]) = ra1;
        *reinterpret_cast<float4*>(&Ws[0][wk0][wn0]) = rw0;
        *reinterpret_cast<float4*>(&Ws[0][wk1][wn1]) = rw1;
    }
    __syncthreads();

    int buf = 0;
    for (int it = 0; it < nIters; it++) {
        const bool has_next = (it + 1) < nIters;
        float4 ra0, ra1, rw0, rw1;
        if (has_next) {
            const int ko = (it + 1) * 32;
            ra0 = *reinterpret_cast<const float4*>(Ap0 + ko);
            ra1 = *reinterpret_cast<const float4*>(Ap1 + ko);
            rw0 = *reinterpret_cast<const float4*>(Wp0 + (size_t)ko * N);
            rw1 = *reinterpret_cast<const float4*>(Wp1 + (size_t)ko * N);
        }
        // ---- compute on buf
#pragma unroll
        for (int kk = 0; kk < 32; kk++) {
            float4 wv = *reinterpret_cast<const float4*>(&Ws[buf][kk][tx * 4]);
            float av0 = As[buf][ty * 4 + 0][kk];
            float av1 = As[buf][ty * 4 + 1][kk];
            float av2 = As[buf][ty * 4 + 2][kk];
            float av3 = As[buf][ty * 4 + 3][kk];
            acc[0][0] = fmaf(av0, wv.x, acc[0][0]);
            acc[0][1] = fmaf(av0, wv.y, acc[0][1]);
            acc[0][2] = fmaf(av0, wv.z, acc[0][2]);
            acc[0][3] = fmaf(av0, wv.w, acc[0][3]);
            acc[1][0] = fmaf(av1, wv.x, acc[1][0]);
            acc[1][1] = fmaf(av1, wv.y, acc[1][1]);
            acc[1][2] = fmaf(av1, wv.z, acc[1][2]);
            acc[1][3] = fmaf(av1, wv.w, acc[1][3]);
            acc[2][0] = fmaf(av2, wv.x, acc[2][0]);
            acc[2][1] = fmaf(av2, wv.y, acc[2][1]);
            acc[2][2] = fmaf(av2, wv.z, acc[2][2]);
            acc[2][3] = fmaf(av2, wv.w, acc[2][3]);
            acc[3][0] = fmaf(av3, wv.x, acc[3][0]);
            acc[3][1] = fmaf(av3, wv.y, acc[3][1]);
            acc[3][2] = fmaf(av3, wv.z, acc[3][2]);
            acc[3][3] = fmaf(av3, wv.w, acc[3][3]);
        }
        if (has_next) {
            int nb = buf ^ 1;
            *reinterpret_cast<float4*>(&As[nb][am0][ak0]) = ra0;
            *reinterpret_cast<float4*>(&As[nb][am1][ak1]) = ra1;
            *reinterpret_cast<float4*>(&Ws[nb][wk0][wn0]) = rw0;
            *reinterpret_cast<float4*>(&Ws[nb][wk1][wn1]) = rw1;
            __syncthreads();
            buf = nb;
        }
    }

    // ---- epilogue
    if (splitk == 1) {
        const float* bias = g ? b1 : b0;
        float* C = g ? C1 : C0;
#pragma unroll
        for (int i = 0; i < 4; i++) {
            int m = brow + ty * 4 + i;
            int n = bcol + tx * 4;
            float4 bv = *reinterpret_cast<const float4*>(&bias[n]);
            float4 o;
            o.x = acc[i][0] + bv.x;
            o.y = acc[i][1] + bv.y;
            o.z = acc[i][2] + bv.z;
            o.w = acc[i][3] + bv.w;
            *reinterpret_cast<float4*>(&C[(size_t)m * N + n]) = o;
        }
    } else {
        float* P = g_part + (size_t)z * M * N;
#pragma unroll
        for (int i = 0; i < 4; i++) {
            int m = brow + ty * 4 + i;
            int n = bcol + tx * 4;
            float4 o;
            o.x = acc[i][0]; o.y = acc[i][1]; o.z = acc[i][2]; o.w = acc[i][3];
            *reinterpret_cast<float4*>(&P[(size_t)m * N + n]) = o;
        }
    }
}

// ---------------- split-K reduction for layer-2 pair (splitk=2) ----------------
__global__ __launch_bounds__(256)
void reduce_split2(const float* __restrict__ b0, const float* __restrict__ b1) {
    const int MN = NN * HD2;          // 262144
    int idx = blockIdx.x * 256 + threadIdx.x;
    if (idx < MN) {
        int n = idx & (HD2 - 1);
        g_xl2[idx] = g_part[idx] + g_part[idx + MN] + b0[n];
        g_xr2[idx] = g_part[idx + 2 * MN] + g_part[idx + 3 * MN] + b1[n];
    }
}

// ---------------- GATv2 attention: one block = 8 targets x 1 head ----------------
template <int D, int ACT>
__global__ __launch_bounds__(256)
void gatv2_attn2(const float* __restrict__ xl, const float* __restrict__ xr,
                 const float* __restrict__ att, const float* __restrict__ bias,
                 float* __restrict__ out) {
    const int IT = 8;
    const int h    = blockIdx.x & 3;
    const int i0   = (blockIdx.x >> 2) * IT;
    const int tid  = threadIdx.x;
    const int lane = tid & 31, w = tid >> 5;
    const int HD   = NH * D;

    __shared__ float s_att[D];
    __shared__ float s_xr[IT][D];
    __shared__ float s_s[IT][NN];

    for (int d = tid; d < D; d += 256) s_att[d] = att[h * D + d];
    for (int idx = tid; idx < IT * D; idx += 256) {
        int it = idx / D, d = idx % D;
        s_xr[it][d] = xr[(i0 + it) * HD + h * D + d];
    }
    __syncthreads();

    // ---- scores: warp w handles sources j = w*32 .. w*32+31
    for (int t = 0; t < 32; t++) {
        int j = w * 32 + t;
        const float* xlj = xl + j * HD + h * D;
        float acc[IT];
#pragma unroll
        for (int it = 0; it < IT; it++) acc[it] = 0.f;
        for (int k = lane; k < D; k += 32) {
            float xlv   = __ldg(xlj + k);
            float attv  = s_att[k];
            float attv2 = 0.2f * attv;
#pragma unroll
            for (int it = 0; it < IT; it++) {
                float zz = s_xr[it][k] + xlv;
                float c = (zz > 0.f) ? attv : attv2;
                acc[it] = fmaf(c, zz, acc[it]);
            }
        }
#pragma unroll
        for (int it = 0; it < IT; it++) {
            float v = acc[it];
#pragma unroll
            for (int o = 16; o; o >>= 1) v += __shfl_xor_sync(0xffffffffu, v, o);
            acc[it] = v;
        }
        if (lane == 0) {
#pragma unroll
            for (int it = 0; it < IT; it++)
                s_s[it][j] = (j == i0 + it) ? -INFINITY : acc[it];
        }
    }
    __syncthreads();

    // ---- softmax: warp w normalizes target w's row
    {
        float v[8];
#pragma unroll
        for (int q = 0; q < 8; q++) v[q] = s_s[w][lane + 32 * q];
        float m = v[0];
#pragma unroll
        for (int q = 1; q < 8; q++) m = fmaxf(m, v[q]);
#pragma unroll
        for (int o = 16; o; o >>= 1) m = fmaxf(m, __shfl_xor_sync(0xffffffffu, m, o));
        float ssum = 0.f;
#pragma unroll
        for (int q = 0; q < 8; q++) { v[q] = expf(v[q] - m); ssum += v[q]; }
#pragma unroll
        for (int o = 16; o; o >>= 1) ssum += __shfl_xor_sync(0xffffffffu, ssum, o);
        float inv = 1.f / ssum;
#pragma unroll
        for (int q = 0; q < 8; q++) s_s[w][lane + 32 * q] = v[q] * inv;
    }
    __syncthreads();

    // ---- aggregate
    for (int d0 = 0; d0 < D; d0 += 256) {
        int d = d0 + tid;
        float acc[IT];
#pragma unroll
        for (int it = 0; it < IT; it++) acc[it] = 0.f;
        const float* xp = xl + h * D + d;
        for (int j = 0; j < NN; j++) {
            float xv = __ldg(xp + j * HD);
#pragma unroll
            for (int it = 0; it < IT; it++)
                acc[it] = fmaf(s_s[it][j], xv, acc[it]);
        }
        float bv = bias[h * D + d];
#pragma unroll
        for (int it = 0; it < IT; it++) {
            float o_ = acc[it] + bv;
            if (ACT == 1) o_ = o_ > 0.f ? o_ : expm1f(o_);
            out[(i0 + it) * HD + h * D + d] = o_;
        }
    }
}

// ------- LayerNorm + ReLU + residual, rows 0..127; sums Wout's 8 split-K partials
__global__ __launch_bounds__(256)
void ln_residual(const float* __restrict__ bout,
                 const float* __restrict__ ln_g, const float* __restrict__ ln_b,
                 const float* __restrict__ rw, float* __restrict__ out) {
    const int i = blockIdx.x;                 // 0..127
    const int tid = threadIdx.x;              // 256
    const int lane = tid & 31, warp = tid >> 5;
    const int MN = 128 * FDIM;                // per-partial size
    __shared__ float s_red1[8], s_red2[8];
    __shared__ float s_mu, s_rstd;

    float yv[4];
    float sum = 0.f, sq = 0.f;
#pragma unroll
    for (int q = 0; q < 4; q++) {
        int c = tid + q * 256;
        float v = bout[c];
#pragma unroll
        for (int s = 0; s < 8; s++)
            v += g_part[s * MN + i * FDIM + c];
        yv[q] = v;
        sum += v; sq += v * v;
    }
#pragma unroll
    for (int o = 16; o; o >>= 1) {
        sum += __shfl_xor_sync(0xffffffffu, sum, o);
        sq  += __shfl_xor_sync(0xffffffffu, sq,  o);
    }
    if (lane == 0) { s_red1[warp] = sum; s_red2[warp] = sq; }
    __syncthreads();
    if (tid == 0) {
        float ts = 0.f, tq = 0.f;
        for (int w = 0; w < 8; w++) { ts += s_red1[w]; tq += s_red2[w]; }
        float mu = ts / FDIM;
        float var = tq / FDIM - mu * mu;
        s_mu = mu;
        s_rstd = rsqrtf(var + 1e-5f);
    }
    __syncthreads();
    float mu = s_mu, rstd = s_rstd, w0 = rw[0];
#pragma unroll
    for (int q = 0; q < 4; q++) {
        int c = tid + q * 256;
        float v = (yv[q] - mu) * rstd * ln_g[c] + ln_b[c];
        v = fmaxf(v, 0.f);
        out[i * FDIM + c] = v + w0 * g_x[i * FDIM + c];
    }
}

// ---------------- launch ----------------
extern "C" void kernel_launch(void* const* d_in, const int* in_sizes, int n_in,
                              void* d_out, int out_size) {
    (void)in_sizes; (void)n_in; (void)out_size;
    const float* v1f   = (const float*)d_in[0];
    const float* v2f   = (const float*)d_in[1];
    const float* v1fu  = (const float*)d_in[2];
    const float* v2fu  = (const float*)d_in[3];
    const float* Wl1   = (const float*)d_in[4];
    const float* bl1   = (const float*)d_in[5];
    const float* Wr1   = (const float*)d_in[6];
    const float* br1   = (const float*)d_in[7];
    const float* att1  = (const float*)d_in[8];
    const float* bias1 = (const float*)d_in[9];
    const float* Wl2   = (const float*)d_in[10];
    const float* bl2   = (const float*)d_in[11];
    const float* Wr2   = (const float*)d_in[12];
    const float* br2   = (const float*)d_in[13];
    const float* att2  = (const float*)d_in[14];
    const float* bias2 = (const float*)d_in[15];
    const float* Wout  = (const float*)d_in[16];
    const float* bout  = (const float*)d_in[17];
    const float* ln_g  = (const float*)d_in[18];
    const float* ln_b  = (const float*)d_in[19];
    const float* rw    = (const float*)d_in[20];
    float* out = (float*)d_out;

    float *x, *xl1, *xr1, *o1, *xl2, *xr2, *o2;
    cudaGetSymbolAddress((void**)&x,   g_x);
    cudaGetSymbolAddress((void**)&xl1, g_xl1);
    cudaGetSymbolAddress((void**)&xr1, g_xr1);
    cudaGetSymbolAddress((void**)&o1,  g_o1);
    cudaGetSymbolAddress((void**)&xl2, g_xl2);
    cudaGetSymbolAddress((void**)&xr2, g_xr2);
    cudaGetSymbolAddress((void**)&o2,  g_o2);

    concat_kernel<<<(64 * FDIM + 255) / 256, 256>>>(v1f, v2f, v1fu, v2fu);

    // GAT layer 1: x[256,1024] @ {Wl1,Wr1}[1024,2048]; 256 CTAs, no split
    {
        dim3 grid(HD1 / 64, NN / 64, 2);
        gemm_pipe<<<grid, 256>>>(x, Wl1, Wr1, bl1, br1, xl1, xr1, NN, FDIM, HD1, 1);
    }
    gatv2_attn2<HIDD, 1><<<(NN / 8) * NH, 256>>>(xl1, xr1, att1, bias1, o1);

    // GAT layer 2: o1[256,2048] @ {Wl2,Wr2}[2048,1024]; split-K=2 -> 256 CTAs
    {
        dim3 grid(HD2 / 64, NN / 64, 4);
        gemm_pipe<<<grid, 256>>>(o1, Wl2, Wr2, bl2, br2, xl2, xr2, NN, HD1, HD2, 2);
    }
    reduce_split2<<<(NN * HD2 + 255) / 256, 256>>>(bl2, br2);
    gatv2_attn2<DD2, 0><<<(NN / 8) * NH, 256>>>(xl2, xr2, att2, bias2, o2);

    // Output projection rows 0..127: split-K=8 -> 256 CTAs, partials summed in LN
    {
        dim3 grid(FDIM / 64, 128 / 64, 8);
        gemm_pipe<<<grid, 256>>>(o2, Wout, Wout, bout, bout, nullptr, nullptr,
                                 128, FDIM, FDIM, 8);
    }
    ln_residual<<<128, 256>>>(bout, ln_g, ln_b, rw, out);
}

// round 4
// speedup vs baseline: 3.0294x; 1.0191x over previous
#include <cuda_runtime.h>
#include <math.h>

#define NN   256      // total graph nodes
#define FDIM 1024
#define HIDD 512
#define NH   4
#define DD2  256
#define HD1  2048     // NH*HIDD
#define HD2  1024     // NH*DD2

// ---- device scratch (no allocations allowed) ----
__device__ float g_x  [NN * FDIM];
__device__ float g_xl1[NN * HD1];
__device__ float g_xr1[NN * HD1];
__device__ float g_o1 [NN * HD1];
__device__ float g_xl2[NN * HD2];
__device__ float g_xr2[NN * HD2];
__device__ float g_o2 [NN * HD2];
__device__ float g_part[1 << 21];   // 8 MB split-K partials

// ---------------- concat inputs into x [256,1024] ----------------
__global__ void concat_kernel(const float* __restrict__ a, const float* __restrict__ b,
                              const float* __restrict__ c, const float* __restrict__ d) {
    int idx = blockIdx.x * blockDim.x + threadIdx.x;
    if (idx < 64 * FDIM) {
        g_x[idx]              = a[idx];
        g_x[64  * FDIM + idx] = b[idx];
        g_x[128 * FDIM + idx] = c[idx];
        g_x[192 * FDIM + idx] = d[idx];
    }
}

// ---------------- pipelined fp32 GEMM, 64x64 tile, BK=32, split-K, dual-GEMM ----
// A tile stored k-major so compute reads are 2x LDS.128 per k-step.
// z = gemm_idx * splitk + split. If splitk==1 writes C{g} with bias, else writes
// partial to g_part + z*M*N (bias added in the reduction).
__global__ __launch_bounds__(256)
void gemm_pipe(const float* __restrict__ A,
               const float* __restrict__ W0, const float* __restrict__ W1,
               const float* __restrict__ b0, const float* __restrict__ b1,
               float* __restrict__ C0, float* __restrict__ C1,
               int M, int K, int N, int splitk) {
    const int z = blockIdx.z;
    const int g = z / splitk;
    const int s = z % splitk;
    const float* W = g ? W1 : W0;
    const int kspan = K / splitk;
    const int kbeg  = s * kspan;
    const int nIters = kspan / 32;

    __shared__ __align__(16) float As[2][32][68];   // k-major, padded (68%4==0)
    __shared__ __align__(16) float Ws[2][32][64];   // k-major

    const int brow = blockIdx.y * 64;
    const int bcol = blockIdx.x * 64;
    const int tid  = threadIdx.x;
    const int tx   = tid & 15;        // 16 cols of threads (4 floats each)
    const int ty   = tid >> 4;        // 16 rows of threads (4 rows each)

    // global load coordinates (2 float4 per thread for each of A and W)
    const int aIdx0 = tid * 4;              // over 64*32 = 2048
    const int aIdx1 = aIdx0 + 1024;
    const int am0 = aIdx0 >> 5, ak0 = aIdx0 & 31;
    const int am1 = aIdx1 >> 5, ak1 = aIdx1 & 31;
    const int wIdx0 = tid * 4;              // over 32*64 = 2048
    const int wIdx1 = wIdx0 + 1024;
    const int wk0 = wIdx0 >> 6, wn0 = wIdx0 & 63;
    const int wk1 = wIdx1 >> 6, wn1 = wIdx1 & 63;

    const float* Ap0 = A + (size_t)(brow + am0) * K + kbeg + ak0;
    const float* Ap1 = A + (size_t)(brow + am1) * K + kbeg + ak1;
    const float* Wp0 = W + (size_t)(kbeg + wk0) * N + bcol + wn0;
    const float* Wp1 = W + (size_t)(kbeg + wk1) * N + bcol + wn1;

    float acc[4][4];
#pragma unroll
    for (int i = 0; i < 4; i++)
#pragma unroll
        for (int j = 0; j < 4; j++) acc[i][j] = 0.f;

    // ---- preload tile 0 into buffer 0 (A transposed to k-major)
    {
        float4 ra0 = *reinterpret_cast<const float4*>(Ap0);
        float4 ra1 = *reinterpret_cast<const float4*>(Ap1);
        float4 rw0 = *reinterpret_cast<const float4*>(Wp0);
        float4 rw1 = *reinterpret_cast<const float4*>(Wp1);
        As[0][ak0 + 0][am0] = ra0.x;
        As[0][ak0 + 1][am0] = ra0.y;
        As[0][ak0 + 2][am0] = ra0.z;
        As[0][ak0 + 3][am0] = ra0.w;
        As[0][ak1 + 0][am1] = ra1.x;
        As[0][ak1 + 1][am1] = ra1.y;
        As[0][ak1 + 2][am1] = ra1.z;
        As[0][ak1 + 3][am1] = ra1.w;
        *reinterpret_cast<float4*>(&Ws[0][wk0][wn0]) = rw0;
        *reinterpret_cast<float4*>(&Ws[0][wk1][wn1]) = rw1;
    }
    __syncthreads();

    int buf = 0;
    for (int it = 0; it < nIters; it++) {
        const bool has_next = (it + 1) < nIters;
        float4 ra0, ra1, rw0, rw1;
        if (has_next) {
            const int ko = (it + 1) * 32;
            ra0 = *reinterpret_cast<const float4*>(Ap0 + ko);
            ra1 = *reinterpret_cast<const float4*>(Ap1 + ko);
            rw0 = *reinterpret_cast<const float4*>(Wp0 + (size_t)ko * N);
            rw1 = *reinterpret_cast<const float4*>(Wp1 + (size_t)ko * N);
        }
        // ---- compute on buf: per kk, 2x LDS.128 + 16 FFMA
#pragma unroll
        for (int kk = 0; kk < 32; kk++) {
            float4 av = *reinterpret_cast<const float4*>(&As[buf][kk][ty * 4]);
            float4 wv = *reinterpret_cast<const float4*>(&Ws[buf][kk][tx * 4]);
            acc[0][0] = fmaf(av.x, wv.x, acc[0][0]);
            acc[0][1] = fmaf(av.x, wv.y, acc[0][1]);
            acc[0][2] = fmaf(av.x, wv.z, acc[0][2]);
            acc[0][3] = fmaf(av.x, wv.w, acc[0][3]);
            acc[1][0] = fmaf(av.y, wv.x, acc[1][0]);
            acc[1][1] = fmaf(av.y, wv.y, acc[1][1]);
            acc[1][2] = fmaf(av.y, wv.z, acc[1][2]);
            acc[1][3] = fmaf(av.y, wv.w, acc[1][3]);
            acc[2][0] = fmaf(av.z, wv.x, acc[2][0]);
            acc[2][1] = fmaf(av.z, wv.y, acc[2][1]);
            acc[2][2] = fmaf(av.z, wv.z, acc[2][2]);
            acc[2][3] = fmaf(av.z, wv.w, acc[2][3]);
            acc[3][0] = fmaf(av.w, wv.x, acc[3][0]);
            acc[3][1] = fmaf(av.w, wv.y, acc[3][1]);
            acc[3][2] = fmaf(av.w, wv.z, acc[3][2]);
            acc[3][3] = fmaf(av.w, wv.w, acc[3][3]);
        }
        if (has_next) {
            int nb = buf ^ 1;
            As[nb][ak0 + 0][am0] = ra0.x;
            As[nb][ak0 + 1][am0] = ra0.y;
            As[nb][ak0 + 2][am0] = ra0.z;
            As[nb][ak0 + 3][am0] = ra0.w;
            As[nb][ak1 + 0][am1] = ra1.x;
            As[nb][ak1 + 1][am1] = ra1.y;
            As[nb][ak1 + 2][am1] = ra1.z;
            As[nb][ak1 + 3][am1] = ra1.w;
            *reinterpret_cast<float4*>(&Ws[nb][wk0][wn0]) = rw0;
            *reinterpret_cast<float4*>(&Ws[nb][wk1][wn1]) = rw1;
            __syncthreads();
            buf = nb;
        }
    }

    // ---- epilogue
    if (splitk == 1) {
        const float* bias = g ? b1 : b0;
        float* C = g ? C1 : C0;
#pragma unroll
        for (int i = 0; i < 4; i++) {
            int m = brow + ty * 4 + i;
            int n = bcol + tx * 4;
            float4 bv = *reinterpret_cast<const float4*>(&bias[n]);
            float4 o;
            o.x = acc[i][0] + bv.x;
            o.y = acc[i][1] + bv.y;
            o.z = acc[i][2] + bv.z;
            o.w = acc[i][3] + bv.w;
            *reinterpret_cast<float4*>(&C[(size_t)m * N + n]) = o;
        }
    } else {
        float* P = g_part + (size_t)z * M * N;
#pragma unroll
        for (int i = 0; i < 4; i++) {
            int m = brow + ty * 4 + i;
            int n = bcol + tx * 4;
            float4 o;
            o.x = acc[i][0]; o.y = acc[i][1]; o.z = acc[i][2]; o.w = acc[i][3];
            *reinterpret_cast<float4*>(&P[(size_t)m * N + n]) = o;
        }
    }
}

// ---- split-K reductions ----
// layer1: splitk=2, two gemms; slices [g0s0, g0s1, g1s0, g1s1], MN = 256*2048
__global__ __launch_bounds__(256)
void reduce_l1(const float* __restrict__ b0, const float* __restrict__ b1) {
    const int MN = NN * HD1;
    int idx = blockIdx.x * 256 + threadIdx.x;
    if (idx < MN) {
        int n = idx & (HD1 - 1);
        g_xl1[idx] = g_part[idx] + g_part[idx + MN] + b0[n];
        g_xr1[idx] = g_part[idx + 2 * MN] + g_part[idx + 3 * MN] + b1[n];
    }
}
// layer2: splitk=4, two gemms; slices [g0s0..g0s3, g1s0..g1s3], MN = 256*1024
__global__ __launch_bounds__(256)
void reduce_l2(const float* __restrict__ b0, const float* __restrict__ b1) {
    const int MN = NN * HD2;
    int idx = blockIdx.x * 256 + threadIdx.x;
    if (idx < MN) {
        int n = idx & (HD2 - 1);
        float a = g_part[idx] + g_part[idx + MN] + g_part[idx + 2 * MN] + g_part[idx + 3 * MN];
        float b = g_part[idx + 4 * MN] + g_part[idx + 5 * MN] + g_part[idx + 6 * MN] + g_part[idx + 7 * MN];
        g_xl2[idx] = a + b0[n];
        g_xr2[idx] = b + b1[n];
    }
}

// ---------------- GATv2 attention: one block = 8 targets x 1 head ----------------
template <int D, int ACT>
__global__ __launch_bounds__(256)
void gatv2_attn2(const float* __restrict__ xl, const float* __restrict__ xr,
                 const float* __restrict__ att, const float* __restrict__ bias,
                 float* __restrict__ out) {
    const int IT = 8;
    const int h    = blockIdx.x & 3;
    const int i0   = (blockIdx.x >> 2) * IT;
    const int tid  = threadIdx.x;
    const int lane = tid & 31, w = tid >> 5;
    const int HD   = NH * D;

    __shared__ float s_att[D];
    __shared__ float s_xr[IT][D];
    __shared__ float s_s[IT][NN];

    for (int d = tid; d < D; d += 256) s_att[d] = att[h * D + d];
    for (int idx = tid; idx < IT * D; idx += 256) {
        int it = idx / D, d = idx % D;
        s_xr[it][d] = xr[(i0 + it) * HD + h * D + d];
    }
    __syncthreads();

    // ---- scores: warp w handles sources j = w*32 .. w*32+31
    for (int t = 0; t < 32; t++) {
        int j = w * 32 + t;
        const float* xlj = xl + j * HD + h * D;
        float acc[IT];
#pragma unroll
        for (int it = 0; it < IT; it++) acc[it] = 0.f;
        for (int k = lane; k < D; k += 32) {
            float xlv   = __ldg(xlj + k);
            float attv  = s_att[k];
            float attv2 = 0.2f * attv;
#pragma unroll
            for (int it = 0; it < IT; it++) {
                float zz = s_xr[it][k] + xlv;
                float c = (zz > 0.f) ? attv : attv2;
                acc[it] = fmaf(c, zz, acc[it]);
            }
        }
#pragma unroll
        for (int it = 0; it < IT; it++) {
            float v = acc[it];
#pragma unroll
            for (int o = 16; o; o >>= 1) v += __shfl_xor_sync(0xffffffffu, v, o);
            acc[it] = v;
        }
        if (lane == 0) {
#pragma unroll
            for (int it = 0; it < IT; it++)
                s_s[it][j] = (j == i0 + it) ? -INFINITY : acc[it];
        }
    }
    __syncthreads();

    // ---- softmax: warp w normalizes target w's row
    {
        float v[8];
#pragma unroll
        for (int q = 0; q < 8; q++) v[q] = s_s[w][lane + 32 * q];
        float m = v[0];
#pragma unroll
        for (int q = 1; q < 8; q++) m = fmaxf(m, v[q]);
#pragma unroll
        for (int o = 16; o; o >>= 1) m = fmaxf(m, __shfl_xor_sync(0xffffffffu, m, o));
        float ssum = 0.f;
#pragma unroll
        for (int q = 0; q < 8; q++) { v[q] = expf(v[q] - m); ssum += v[q]; }
#pragma unroll
        for (int o = 16; o; o >>= 1) ssum += __shfl_xor_sync(0xffffffffu, ssum, o);
        float inv = 1.f / ssum;
#pragma unroll
        for (int q = 0; q < 8; q++) s_s[w][lane + 32 * q] = v[q] * inv;
    }
    __syncthreads();

    // ---- aggregate
    for (int d0 = 0; d0 < D; d0 += 256) {
        int d = d0 + tid;
        float acc[IT];
#pragma unroll
        for (int it = 0; it < IT; it++) acc[it] = 0.f;
        const float* xp = xl + h * D + d;
        for (int j = 0; j < NN; j++) {
            float xv = __ldg(xp + j * HD);
#pragma unroll
            for (int it = 0; it < IT; it++)
                acc[it] = fmaf(s_s[it][j], xv, acc[it]);
        }
        float bv = bias[h * D + d];
#pragma unroll
        for (int it = 0; it < IT; it++) {
            float o_ = acc[it] + bv;
            if (ACT == 1) o_ = o_ > 0.f ? o_ : expm1f(o_);
            out[(i0 + it) * HD + h * D + d] = o_;
        }
    }
}

// ------- LayerNorm + ReLU + residual, rows 0..127; sums Wout's 8 split-K partials
__global__ __launch_bounds__(256)
void ln_residual(const float* __restrict__ bout,
                 const float* __restrict__ ln_g, const float* __restrict__ ln_b,
                 const float* __restrict__ rw, float* __restrict__ out) {
    const int i = blockIdx.x;                 // 0..127
    const int tid = threadIdx.x;              // 256
    const int lane = tid & 31, warp = tid >> 5;
    const int MN = 128 * FDIM;                // per-partial size
    __shared__ float s_red1[8], s_red2[8];
    __shared__ float s_mu, s_rstd;

    float yv[4];
    float sum = 0.f, sq = 0.f;
#pragma unroll
    for (int q = 0; q < 4; q++) {
        int c = tid + q * 256;
        float v = bout[c];
#pragma unroll
        for (int s = 0; s < 8; s++)
            v += g_part[s * MN + i * FDIM + c];
        yv[q] = v;
        sum += v; sq += v * v;
    }
#pragma unroll
    for (int o = 16; o; o >>= 1) {
        sum += __shfl_xor_sync(0xffffffffu, sum, o);
        sq  += __shfl_xor_sync(0xffffffffu, sq,  o);
    }
    if (lane == 0) { s_red1[warp] = sum; s_red2[warp] = sq; }
    __syncthreads();
    if (tid == 0) {
        float ts = 0.f, tq = 0.f;
        for (int w = 0; w < 8; w++) { ts += s_red1[w]; tq += s_red2[w]; }
        float mu = ts / FDIM;
        float var = tq / FDIM - mu * mu;
        s_mu = mu;
        s_rstd = rsqrtf(var + 1e-5f);
    }
    __syncthreads();
    float mu = s_mu, rstd = s_rstd, w0 = rw[0];
#pragma unroll
    for (int q = 0; q < 4; q++) {
        int c = tid + q * 256;
        float v = (yv[q] - mu) * rstd * ln_g[c] + ln_b[c];
        v = fmaxf(v, 0.f);
        out[i * FDIM + c] = v + w0 * g_x[i * FDIM + c];
    }
}

// ---------------- launch ----------------
extern "C" void kernel_launch(void* const* d_in, const int* in_sizes, int n_in,
                              void* d_out, int out_size) {
    (void)in_sizes; (void)n_in; (void)out_size;
    const float* v1f   = (const float*)d_in[0];
    const float* v2f   = (const float*)d_in[1];
    const float* v1fu  = (const float*)d_in[2];
    const float* v2fu  = (const float*)d_in[3];
    const float* Wl1   = (const float*)d_in[4];
    const float* bl1   = (const float*)d_in[5];
    const float* Wr1   = (const float*)d_in[6];
    const float* br1   = (const float*)d_in[7];
    const float* att1  = (const float*)d_in[8];
    const float* bias1 = (const float*)d_in[9];
    const float* Wl2   = (const float*)d_in[10];
    const float* bl2   = (const float*)d_in[11];
    const float* Wr2   = (const float*)d_in[12];
    const float* br2   = (const float*)d_in[13];
    const float* att2  = (const float*)d_in[14];
    const float* bias2 = (const float*)d_in[15];
    const float* Wout  = (const float*)d_in[16];
    const float* bout  = (const float*)d_in[17];
    const float* ln_g  = (const float*)d_in[18];
    const float* ln_b  = (const float*)d_in[19];
    const float* rw    = (const float*)d_in[20];
    float* out = (float*)d_out;

    float *x, *xl1, *xr1, *o1, *xl2, *xr2, *o2;
    cudaGetSymbolAddress((void**)&x,   g_x);
    cudaGetSymbolAddress((void**)&xl1, g_xl1);
    cudaGetSymbolAddress((void**)&xr1, g_xr1);
    cudaGetSymbolAddress((void**)&o1,  g_o1);
    cudaGetSymbolAddress((void**)&xl2, g_xl2);
    cudaGetSymbolAddress((void**)&xr2, g_xr2);
    cudaGetSymbolAddress((void**)&o2,  g_o2);

    concat_kernel<<<(64 * FDIM + 255) / 256, 256>>>(v1f, v2f, v1fu, v2fu);

    // GAT layer 1: x[256,1024] @ {Wl1,Wr1}[1024,2048]; split-K=2 -> 512 CTAs
    {
        dim3 grid(HD1 / 64, NN / 64, 4);
        gemm_pipe<<<grid, 256>>>(x, Wl1, Wr1, nullptr, nullptr, nullptr, nullptr,
                                 NN, FDIM, HD1, 2);
    }
    reduce_l1<<<(NN * HD1 + 255) / 256, 256>>>(bl1, br1);
    gatv2_attn2<HIDD, 1><<<(NN / 8) * NH, 256>>>(xl1, xr1, att1, bias1, o1);

    // GAT layer 2: o1[256,2048] @ {Wl2,Wr2}[2048,1024]; split-K=4 -> 512 CTAs
    {
        dim3 grid(HD2 / 64, NN / 64, 8);
        gemm_pipe<<<grid, 256>>>(o1, Wl2, Wr2, nullptr, nullptr, nullptr, nullptr,
                                 NN, HD1, HD2, 4);
    }
    reduce_l2<<<(NN * HD2 + 255) / 256, 256>>>(bl2, br2);
    gatv2_attn2<DD2, 0><<<(NN / 8) * NH, 256>>>(xl2, xr2, att2, bias2, o2);

    // Output projection rows 0..127: split-K=8 -> 256 CTAs, partials summed in LN
    {
        dim3 grid(FDIM / 64, 128 / 64, 8);
        gemm_pipe<<<grid, 256>>>(o2, Wout, Wout, nullptr, nullptr, nullptr, nullptr,
                                 128, FDIM, FDIM, 8);
    }
    ln_residual<<<128, 256>>>(bout, ln_g, ln_b, rw, out);
}

// round 5
// speedup vs baseline: 4.6466x; 1.5338x over previous
#include <cuda_runtime.h>
#include <math.h>

#define NN   256      // total graph nodes
#define FDIM 1024
#define HIDD 512
#define NH   4
#define DD2  256
#define HD1  2048     // NH*HIDD
#define HD2  1024     // NH*DD2

// ---- device scratch (no allocations allowed) ----
__device__ float g_x  [NN * FDIM];
__device__ float g_xl1[NN * HD1];
__device__ float g_xr1[NN * HD1];
__device__ float g_o1 [NN * HD1];
__device__ float g_xl2[NN * HD2];
__device__ float g_xr2[NN * HD2];
__device__ float g_o2 [NN * HD2];
__device__ float g_s  [NH * NN * NN];   // attention scores / weights, 1 MB
__device__ float g_part[1 << 21];       // 8 MB split-K partials

// ---------------- concat inputs into x [256,1024] ----------------
__global__ void concat_kernel(const float* __restrict__ a, const float* __restrict__ b,
                              const float* __restrict__ c, const float* __restrict__ d) {
    int idx = blockIdx.x * blockDim.x + threadIdx.x;
    if (idx < 64 * FDIM) {
        g_x[idx]              = a[idx];
        g_x[64  * FDIM + idx] = b[idx];
        g_x[128 * FDIM + idx] = c[idx];
        g_x[192 * FDIM + idx] = d[idx];
    }
}

// ---------------- pipelined fp32 GEMM, 64x64 tile, BK=32, split-K, dual-GEMM ----
__global__ __launch_bounds__(256)
void gemm_pipe(const float* __restrict__ A,
               const float* __restrict__ W0, const float* __restrict__ W1,
               int M, int K, int N, int splitk) {
    const int z = blockIdx.z;
    const int g = z / splitk;
    const int s = z % splitk;
    const float* W = g ? W1 : W0;
    const int kspan = K / splitk;
    const int kbeg  = s * kspan;
    const int nIters = kspan / 32;

    __shared__ __align__(16) float As[2][32][68];
    __shared__ __align__(16) float Ws[2][32][64];

    const int brow = blockIdx.y * 64;
    const int bcol = blockIdx.x * 64;
    const int tid  = threadIdx.x;
    const int tx   = tid & 15;
    const int ty   = tid >> 4;

    const int aIdx0 = tid * 4;
    const int aIdx1 = aIdx0 + 1024;
    const int am0 = aIdx0 >> 5, ak0 = aIdx0 & 31;
    const int am1 = aIdx1 >> 5, ak1 = aIdx1 & 31;
    const int wIdx0 = tid * 4;
    const int wIdx1 = wIdx0 + 1024;
    const int wk0 = wIdx0 >> 6, wn0 = wIdx0 & 63;
    const int wk1 = wIdx1 >> 6, wn1 = wIdx1 & 63;

    const float* Ap0 = A + (size_t)(brow + am0) * K + kbeg + ak0;
    const float* Ap1 = A + (size_t)(brow + am1) * K + kbeg + ak1;
    const float* Wp0 = W + (size_t)(kbeg + wk0) * N + bcol + wn0;
    const float* Wp1 = W + (size_t)(kbeg + wk1) * N + bcol + wn1;

    float acc[4][4];
#pragma unroll
    for (int i = 0; i < 4; i++)
#pragma unroll
        for (int j = 0; j < 4; j++) acc[i][j] = 0.f;

    {
        float4 ra0 = *reinterpret_cast<const float4*>(Ap0);
        float4 ra1 = *reinterpret_cast<const float4*>(Ap1);
        float4 rw0 = *reinterpret_cast<const float4*>(Wp0);
        float4 rw1 = *reinterpret_cast<const float4*>(Wp1);
        As[0][ak0 + 0][am0] = ra0.x;
        As[0][ak0 + 1][am0] = ra0.y;
        As[0][ak0 + 2][am0] = ra0.z;
        As[0][ak0 + 3][am0] = ra0.w;
        As[0][ak1 + 0][am1] = ra1.x;
        As[0][ak1 + 1][am1] = ra1.y;
        As[0][ak1 + 2][am1] = ra1.z;
        As[0][ak1 + 3][am1] = ra1.w;
        *reinterpret_cast<float4*>(&Ws[0][wk0][wn0]) = rw0;
        *reinterpret_cast<float4*>(&Ws[0][wk1][wn1]) = rw1;
    }
    __syncthreads();

    int buf = 0;
    for (int it = 0; it < nIters; it++) {
        const bool has_next = (it + 1) < nIters;
        float4 ra0, ra1, rw0, rw1;
        if (has_next) {
            const int ko = (it + 1) * 32;
            ra0 = *reinterpret_cast<const float4*>(Ap0 + ko);
            ra1 = *reinterpret_cast<const float4*>(Ap1 + ko);
            rw0 = *reinterpret_cast<const float4*>(Wp0 + (size_t)ko * N);
            rw1 = *reinterpret_cast<const float4*>(Wp1 + (size_t)ko * N);
        }
#pragma unroll
        for (int kk = 0; kk < 32; kk++) {
            float4 av = *reinterpret_cast<const float4*>(&As[buf][kk][ty * 4]);
            float4 wv = *reinterpret_cast<const float4*>(&Ws[buf][kk][tx * 4]);
            acc[0][0] = fmaf(av.x, wv.x, acc[0][0]);
            acc[0][1] = fmaf(av.x, wv.y, acc[0][1]);
            acc[0][2] = fmaf(av.x, wv.z, acc[0][2]);
            acc[0][3] = fmaf(av.x, wv.w, acc[0][3]);
            acc[1][0] = fmaf(av.y, wv.x, acc[1][0]);
            acc[1][1] = fmaf(av.y, wv.y, acc[1][1]);
            acc[1][2] = fmaf(av.y, wv.z, acc[1][2]);
            acc[1][3] = fmaf(av.y, wv.w, acc[1][3]);
            acc[2][0] = fmaf(av.z, wv.x, acc[2][0]);
            acc[2][1] = fmaf(av.z, wv.y, acc[2][1]);
            acc[2][2] = fmaf(av.z, wv.z, acc[2][2]);
            acc[2][3] = fmaf(av.z, wv.w, acc[2][3]);
            acc[3][0] = fmaf(av.w, wv.x, acc[3][0]);
            acc[3][1] = fmaf(av.w, wv.y, acc[3][1]);
            acc[3][2] = fmaf(av.w, wv.z, acc[3][2]);
            acc[3][3] = fmaf(av.w, wv.w, acc[3][3]);
        }
        if (has_next) {
            int nb = buf ^ 1;
            As[nb][ak0 + 0][am0] = ra0.x;
            As[nb][ak0 + 1][am0] = ra0.y;
            As[nb][ak0 + 2][am0] = ra0.z;
            As[nb][ak0 + 3][am0] = ra0.w;
            As[nb][ak1 + 0][am1] = ra1.x;
            As[nb][ak1 + 1][am1] = ra1.y;
            As[nb][ak1 + 2][am1] = ra1.z;
            As[nb][ak1 + 3][am1] = ra1.w;
            *reinterpret_cast<float4*>(&Ws[nb][wk0][wn0]) = rw0;
            *reinterpret_cast<float4*>(&Ws[nb][wk1][wn1]) = rw1;
            __syncthreads();
            buf = nb;
        }
    }

    float* P = g_part + (size_t)z * M * N;
#pragma unroll
    for (int i = 0; i < 4; i++) {
        int m = brow + ty * 4 + i;
        int n = bcol + tx * 4;
        float4 o;
        o.x = acc[i][0]; o.y = acc[i][1]; o.z = acc[i][2]; o.w = acc[i][3];
        *reinterpret_cast<float4*>(&P[(size_t)m * N + n]) = o;
    }
}

// ---- split-K reductions ----
__global__ __launch_bounds__(256)
void reduce_l1(const float* __restrict__ b0, const float* __restrict__ b1) {
    const int MN = NN * HD1;
    int idx = blockIdx.x * 256 + threadIdx.x;
    if (idx < MN) {
        int n = idx & (HD1 - 1);
        g_xl1[idx] = g_part[idx] + g_part[idx + MN] + b0[n];
        g_xr1[idx] = g_part[idx + 2 * MN] + g_part[idx + 3 * MN] + b1[n];
    }
}
__global__ __launch_bounds__(256)
void reduce_l2(const float* __restrict__ b0, const float* __restrict__ b1) {
    const int MN = NN * HD2;
    int idx = blockIdx.x * 256 + threadIdx.x;
    if (idx < MN) {
        int n = idx & (HD2 - 1);
        float a = g_part[idx] + g_part[idx + MN] + g_part[idx + 2 * MN] + g_part[idx + 3 * MN];
        float b = g_part[idx + 4 * MN] + g_part[idx + 5 * MN] + g_part[idx + 6 * MN] + g_part[idx + 7 * MN];
        g_xl2[idx] = a + b0[n];
        g_xr2[idx] = b + b1[n];
    }
}

// ---------------- GATv2 scores: 32x32 (i,j) tile per CTA per head ----------------
// s[h,i,j] = sum_d att[h,d] * lrelu(xr[i,h,d] + xl[j,h,d]);  s[h,i,i] = -inf
template <int D>
__global__ __launch_bounds__(256)
void gat_scores(const float* __restrict__ xl, const float* __restrict__ xr,
                const float* __restrict__ att, float* __restrict__ s_out) {
    const int HD = NH * D;
    const int j0 = blockIdx.x * 32;
    const int i0 = blockIdx.y * 32;
    const int h  = blockIdx.z;
    const int tid = threadIdx.x, lane = tid & 31, w = tid >> 5;

    __shared__ float s_xr[64][33];
    __shared__ float s_xl[64][33];
    __shared__ float s_attf[D];

    for (int d = tid; d < D; d += 256) s_attf[d] = att[h * D + d];

    float acc[4] = {0.f, 0.f, 0.f, 0.f};

    for (int d0 = 0; d0 < D; d0 += 64) {
        // load xr tile (32 rows x 64 d) and xl tile, transposed to [d][row]
#pragma unroll
        for (int r = 0; r < 2; r++) {
            int idx = tid + r * 256;           // 0..511
            int row = idx >> 4;                // 0..31
            int kk  = (idx & 15) * 4;          // 0..60
            float4 vr = *reinterpret_cast<const float4*>(
                &xr[(size_t)(i0 + row) * HD + h * D + d0 + kk]);
            s_xr[kk + 0][row] = vr.x;
            s_xr[kk + 1][row] = vr.y;
            s_xr[kk + 2][row] = vr.z;
            s_xr[kk + 3][row] = vr.w;
            float4 vl = *reinterpret_cast<const float4*>(
                &xl[(size_t)(j0 + row) * HD + h * D + d0 + kk]);
            s_xl[kk + 0][row] = vl.x;
            s_xl[kk + 1][row] = vl.y;
            s_xl[kk + 2][row] = vl.z;
            s_xl[kk + 3][row] = vl.w;
        }
        __syncthreads();
#pragma unroll 16
        for (int kk = 0; kk < 64; kk++) {
            float xrv   = s_xr[kk][lane];
            float attv  = s_attf[d0 + kk];
            float attv2 = 0.2f * attv;
#pragma unroll
            for (int q = 0; q < 4; q++) {
                float xlv = s_xl[kk][w * 4 + q];
                float z = xrv + xlv;
                float c = (z > 0.f) ? attv : attv2;
                acc[q] = fmaf(c, z, acc[q]);
            }
        }
        __syncthreads();
    }

    const int i = i0 + lane;
#pragma unroll
    for (int q = 0; q < 4; q++) {
        int j = j0 + w * 4 + q;
        s_out[((size_t)h * NN + i) * NN + j] = (i == j) ? -INFINITY : acc[q];
    }
}

// ---------------- softmax over each (h,i) row of 256 ----------------
__global__ __launch_bounds__(256)
void gat_softmax(float* __restrict__ s) {
    float* row = s + (size_t)blockIdx.x * NN;
    const int tid = threadIdx.x, lane = tid & 31, w = tid >> 5;
    __shared__ float red[8];
    __shared__ float s_m, s_sum;

    float v = row[tid];
    float m = v;
#pragma unroll
    for (int o = 16; o; o >>= 1) m = fmaxf(m, __shfl_xor_sync(0xffffffffu, m, o));
    if (lane == 0) red[w] = m;
    __syncthreads();
    if (tid == 0) {
        float mm = red[0];
        for (int q = 1; q < 8; q++) mm = fmaxf(mm, red[q]);
        s_m = mm;
    }
    __syncthreads();
    float e = expf(v - s_m);
    float ss = e;
#pragma unroll
    for (int o = 16; o; o >>= 1) ss += __shfl_xor_sync(0xffffffffu, ss, o);
    if (lane == 0) red[w] = ss;
    __syncthreads();
    if (tid == 0) {
        float t = 0.f;
        for (int q = 0; q < 8; q++) t += red[q];
        s_sum = t;
    }
    __syncthreads();
    row[tid] = e * (1.f / s_sum);
}

// ------- aggregation GEMM per head: out[i, h*D+n] = sum_j a[h,i,j]*xl[j,h*D+n] ----
// 32x64 tile, BK=32, double buffered; fused bias + optional ELU.
template <int D, int ACT>
__global__ __launch_bounds__(256)
void gat_agg(const float* __restrict__ a, const float* __restrict__ xl,
             const float* __restrict__ bias, float* __restrict__ out) {
    const int HD = NH * D;
    const int h = blockIdx.z;
    const int brow = blockIdx.y * 32;
    const int bcol = blockIdx.x * 64;
    const float* A = a + (size_t)h * NN * NN;
    const float* B = xl + h * D;

    __shared__ __align__(16) float As[2][32][36];
    __shared__ __align__(16) float Ws[2][32][64];

    const int tid = threadIdx.x;
    const int tx = tid & 15, ty = tid >> 4;

    const int aIdx = tid * 4;
    const int am = aIdx >> 5, ak = aIdx & 31;
    const int wIdx0 = tid * 4, wIdx1 = wIdx0 + 1024;
    const int wk0 = wIdx0 >> 6, wn0 = wIdx0 & 63;
    const int wk1 = wIdx1 >> 6, wn1 = wIdx1 & 63;

    const float* Ap  = A + (size_t)(brow + am) * NN + ak;
    const float* Bp0 = B + (size_t)wk0 * HD + bcol + wn0;
    const float* Bp1 = B + (size_t)wk1 * HD + bcol + wn1;

    float acc[2][4];
#pragma unroll
    for (int i = 0; i < 2; i++)
#pragma unroll
        for (int j = 0; j < 4; j++) acc[i][j] = 0.f;

    {
        float4 ra  = *reinterpret_cast<const float4*>(Ap);
        float4 rw0 = *reinterpret_cast<const float4*>(Bp0);
        float4 rw1 = *reinterpret_cast<const float4*>(Bp1);
        As[0][ak + 0][am] = ra.x;
        As[0][ak + 1][am] = ra.y;
        As[0][ak + 2][am] = ra.z;
        As[0][ak + 3][am] = ra.w;
        *reinterpret_cast<float4*>(&Ws[0][wk0][wn0]) = rw0;
        *reinterpret_cast<float4*>(&Ws[0][wk1][wn1]) = rw1;
    }
    __syncthreads();

    int buf = 0;
    const int nIters = NN / 32;   // 8
    for (int it = 0; it < nIters; it++) {
        const bool has_next = (it + 1) < nIters;
        float4 ra, rw0, rw1;
        if (has_next) {
            const int ko = (it + 1) * 32;
            ra  = *reinterpret_cast<const float4*>(Ap + ko);
            rw0 = *reinterpret_cast<const float4*>(Bp0 + (size_t)ko * HD);
            rw1 = *reinterpret_cast<const float4*>(Bp1 + (size_t)ko * HD);
        }
#pragma unroll
        for (int kk = 0; kk < 32; kk++) {
            float2 av = *reinterpret_cast<const float2*>(&As[buf][kk][ty * 2]);
            float4 wv = *reinterpret_cast<const float4*>(&Ws[buf][kk][tx * 4]);
            acc[0][0] = fmaf(av.x, wv.x, acc[0][0]);
            acc[0][1] = fmaf(av.x, wv.y, acc[0][1]);
            acc[0][2] = fmaf(av.x, wv.z, acc[0][2]);
            acc[0][3] = fmaf(av.x, wv.w, acc[0][3]);
            acc[1][0] = fmaf(av.y, wv.x, acc[1][0]);
            acc[1][1] = fmaf(av.y, wv.y, acc[1][1]);
            acc[1][2] = fmaf(av.y, wv.z, acc[1][2]);
            acc[1][3] = fmaf(av.y, wv.w, acc[1][3]);
        }
        if (has_next) {
            int nb = buf ^ 1;
            As[nb][ak + 0][am] = ra.x;
            As[nb][ak + 1][am] = ra.y;
            As[nb][ak + 2][am] = ra.z;
            As[nb][ak + 3][am] = ra.w;
            *reinterpret_cast<float4*>(&Ws[nb][wk0][wn0]) = rw0;
            *reinterpret_cast<float4*>(&Ws[nb][wk1][wn1]) = rw1;
            __syncthreads();
            buf = nb;
        }
    }

    const int n = bcol + tx * 4;
    float4 bv = *reinterpret_cast<const float4*>(&bias[h * D + n]);
#pragma unroll
    for (int i = 0; i < 2; i++) {
        int m = brow + ty * 2 + i;
        float4 o;
        o.x = acc[i][0] + bv.x;
        o.y = acc[i][1] + bv.y;
        o.z = acc[i][2] + bv.z;
        o.w = acc[i][3] + bv.w;
        if (ACT == 1) {
            o.x = o.x > 0.f ? o.x : expm1f(o.x);
            o.y = o.y > 0.f ? o.y : expm1f(o.y);
            o.z = o.z > 0.f ? o.z : expm1f(o.z);
            o.w = o.w > 0.f ? o.w : expm1f(o.w);
        }
        *reinterpret_cast<float4*>(&out[(size_t)m * HD + h * D + n]) = o;
    }
}

// ------- LayerNorm + ReLU + residual, rows 0..127; sums Wout's 8 split-K partials
__global__ __launch_bounds__(256)
void ln_residual(const float* __restrict__ bout,
                 const float* __restrict__ ln_g, const float* __restrict__ ln_b,
                 const float* __restrict__ rw, float* __restrict__ out) {
    const int i = blockIdx.x;
    const int tid = threadIdx.x;
    const int lane = tid & 31, warp = tid >> 5;
    const int MN = 128 * FDIM;
    __shared__ float s_red1[8], s_red2[8];
    __shared__ float s_mu, s_rstd;

    float yv[4];
    float sum = 0.f, sq = 0.f;
#pragma unroll
    for (int q = 0; q < 4; q++) {
        int c = tid + q * 256;
        float v = bout[c];
#pragma unroll
        for (int s = 0; s < 8; s++)
            v += g_part[s * MN + i * FDIM + c];
        yv[q] = v;
        sum += v; sq += v * v;
    }
#pragma unroll
    for (int o = 16; o; o >>= 1) {
        sum += __shfl_xor_sync(0xffffffffu, sum, o);
        sq  += __shfl_xor_sync(0xffffffffu, sq,  o);
    }
    if (lane == 0) { s_red1[warp] = sum; s_red2[warp] = sq; }
    __syncthreads();
    if (tid == 0) {
        float ts = 0.f, tq = 0.f;
        for (int w = 0; w < 8; w++) { ts += s_red1[w]; tq += s_red2[w]; }
        float mu = ts / FDIM;
        float var = tq / FDIM - mu * mu;
        s_mu = mu;
        s_rstd = rsqrtf(var + 1e-5f);
    }
    __syncthreads();
    float mu = s_mu, rstd = s_rstd, w0 = rw[0];
#pragma unroll
    for (int q = 0; q < 4; q++) {
        int c = tid + q * 256;
        float v = (yv[q] - mu) * rstd * ln_g[c] + ln_b[c];
        v = fmaxf(v, 0.f);
        out[i * FDIM + c] = v + w0 * g_x[i * FDIM + c];
    }
}

// ---------------- launch ----------------
extern "C" void kernel_launch(void* const* d_in, const int* in_sizes, int n_in,
                              void* d_out, int out_size) {
    (void)in_sizes; (void)n_in; (void)out_size;
    const float* v1f   = (const float*)d_in[0];
    const float* v2f   = (const float*)d_in[1];
    const float* v1fu  = (const float*)d_in[2];
    const float* v2fu  = (const float*)d_in[3];
    const float* Wl1   = (const float*)d_in[4];
    const float* bl1   = (const float*)d_in[5];
    const float* Wr1   = (const float*)d_in[6];
    const float* br1   = (const float*)d_in[7];
    const float* att1  = (const float*)d_in[8];
    const float* bias1 = (const float*)d_in[9];
    const float* Wl2   = (const float*)d_in[10];
    const float* bl2   = (const float*)d_in[11];
    const float* Wr2   = (const float*)d_in[12];
    const float* br2   = (const float*)d_in[13];
    const float* att2  = (const float*)d_in[14];
    const float* bias2 = (const float*)d_in[15];
    const float* Wout  = (const float*)d_in[16];
    const float* bout  = (const float*)d_in[17];
    const float* ln_g  = (const float*)d_in[18];
    const float* ln_b  = (const float*)d_in[19];
    const float* rw    = (const float*)d_in[20];
    float* out = (float*)d_out;

    float *x, *xl1, *xr1, *o1, *xl2, *xr2, *o2, *sbuf;
    cudaGetSymbolAddress((void**)&x,   g_x);
    cudaGetSymbolAddress((void**)&xl1, g_xl1);
    cudaGetSymbolAddress((void**)&xr1, g_xr1);
    cudaGetSymbolAddress((void**)&o1,  g_o1);
    cudaGetSymbolAddress((void**)&xl2, g_xl2);
    cudaGetSymbolAddress((void**)&xr2, g_xr2);
    cudaGetSymbolAddress((void**)&o2,  g_o2);
    cudaGetSymbolAddress((void**)&sbuf, g_s);

    concat_kernel<<<(64 * FDIM + 255) / 256, 256>>>(v1f, v2f, v1fu, v2fu);

    // ---- GAT layer 1 linear: split-K=2 -> 512 CTAs
    {
        dim3 grid(HD1 / 64, NN / 64, 4);
        gemm_pipe<<<grid, 256>>>(x, Wl1, Wr1, NN, FDIM, HD1, 2);
    }
    reduce_l1<<<(NN * HD1 + 255) / 256, 256>>>(bl1, br1);

    // ---- GAT layer 1 attention
    {
        dim3 grid(NN / 32, NN / 32, NH);
        gat_scores<HIDD><<<grid, 256>>>(xl1, xr1, att1, sbuf);
    }
    gat_softmax<<<NH * NN, 256>>>(sbuf);
    {
        dim3 grid(HIDD / 64, NN / 32, NH);
        gat_agg<HIDD, 1><<<grid, 256>>>(sbuf, xl1, bias1, o1);
    }

    // ---- GAT layer 2 linear: split-K=4 -> 512 CTAs
    {
        dim3 grid(HD2 / 64, NN / 64, 8);
        gemm_pipe<<<grid, 256>>>(o1, Wl2, Wr2, NN, HD1, HD2, 4);
    }
    reduce_l2<<<(NN * HD2 + 255) / 256, 256>>>(bl2, br2);

    // ---- GAT layer 2 attention
    {
        dim3 grid(NN / 32, NN / 32, NH);
        gat_scores<DD2><<<grid, 256>>>(xl2, xr2, att2, sbuf);
    }
    gat_softmax<<<NH * NN, 256>>>(sbuf);
    {
        dim3 grid(DD2 / 64, NN / 32, NH);
        gat_agg<DD2, 0><<<grid, 256>>>(sbuf, xl2, bias2, o2);
    }

    // ---- Output projection rows 0..127: split-K=8 -> 256 CTAs
    {
        dim3 grid(FDIM / 64, 128 / 64, 8);
        gemm_pipe<<<grid, 256>>>(o2, Wout, Wout, 128, FDIM, FDIM, 8);
    }
    ln_residual<<<128, 256>>>(bout, ln_g, ln_b, rw, out);
}

// round 6
// speedup vs baseline: 4.6800x; 1.0072x over previous
#include <cuda_runtime.h>
#include <math.h>

#define NN   256      // total graph nodes
#define FDIM 1024
#define HIDD 512
#define NH   4
#define DD2  256
#define HD1  2048     // NH*HIDD
#define HD2  1024     // NH*DD2

// ---- device scratch (no allocations allowed) ----
__device__ float g_x  [NN * FDIM];
__device__ float g_xl1[NN * HD1];
__device__ float g_xr1[NN * HD1];
__device__ float g_o1 [NN * HD1];
__device__ float g_xl2[NN * HD2];
__device__ float g_xr2[NN * HD2];
__device__ float g_o2 [NN * HD2];
__device__ float g_s  [NH * NN * NN];   // attention scores / weights
__device__ float g_al [NH * NN];        // att . xl per (head, node)
__device__ float g_ar [NH * NN];        // att . xr per (head, node)
__device__ float g_part[1 << 21];       // 8 MB split-K partials

// ---- packed f32x2 helpers (FFMA2: ptxas never emits it, PTX-only path) ----
__device__ __forceinline__ unsigned long long dupf(float x) {
    unsigned long long r;
    asm("mov.b64 %0, {%1, %1};" : "=l"(r) : "f"(x));
    return r;
}
__device__ __forceinline__ void fma2(unsigned long long& acc,
                                     unsigned long long a, unsigned long long b) {
    asm("fma.rn.f32x2 %0, %1, %2, %0;" : "+l"(acc) : "l"(a), "l"(b));
}
__device__ __forceinline__ float2 unpk(unsigned long long v) {
    float2 r;
    asm("mov.b64 {%0, %1}, %2;" : "=f"(r.x), "=f"(r.y) : "l"(v));
    return r;
}

// ---------------- concat inputs into x [256,1024] ----------------
__global__ void concat_kernel(const float* __restrict__ a, const float* __restrict__ b,
                              const float* __restrict__ c, const float* __restrict__ d) {
    int idx = blockIdx.x * blockDim.x + threadIdx.x;
    if (idx < 64 * FDIM) {
        g_x[idx]              = a[idx];
        g_x[64  * FDIM + idx] = b[idx];
        g_x[128 * FDIM + idx] = c[idx];
        g_x[192 * FDIM + idx] = d[idx];
    }
}

// ---------------- pipelined fp32 GEMM, 64x64 tile, BK=32, split-K, dual-GEMM ----
// FFMA2 inner loop: acc packed over j-pairs; W pairs free via ulonglong2 LDS.128.
__global__ __launch_bounds__(256)
void gemm_pipe(const float* __restrict__ A,
               const float* __restrict__ W0, const float* __restrict__ W1,
               int M, int K, int N, int splitk) {
    const int z = blockIdx.z;
    const int g = z / splitk;
    const int s = z % splitk;
    const float* W = g ? W1 : W0;
    const int kspan = K / splitk;
    const int kbeg  = s * kspan;
    const int nIters = kspan / 32;

    __shared__ __align__(16) float As[2][32][68];
    __shared__ __align__(16) float Ws[2][32][64];

    const int brow = blockIdx.y * 64;
    const int bcol = blockIdx.x * 64;
    const int tid  = threadIdx.x;
    const int tx   = tid & 15;
    const int ty   = tid >> 4;

    const int aIdx0 = tid * 4;
    const int aIdx1 = aIdx0 + 1024;
    const int am0 = aIdx0 >> 5, ak0 = aIdx0 & 31;
    const int am1 = aIdx1 >> 5, ak1 = aIdx1 & 31;
    const int wIdx0 = tid * 4;
    const int wIdx1 = wIdx0 + 1024;
    const int wk0 = wIdx0 >> 6, wn0 = wIdx0 & 63;
    const int wk1 = wIdx1 >> 6, wn1 = wIdx1 & 63;

    const float* Ap0 = A + (size_t)(brow + am0) * K + kbeg + ak0;
    const float* Ap1 = A + (size_t)(brow + am1) * K + kbeg + ak1;
    const float* Wp0 = W + (size_t)(kbeg + wk0) * N + bcol + wn0;
    const float* Wp1 = W + (size_t)(kbeg + wk1) * N + bcol + wn1;

    unsigned long long accP[4][2];   // [i][j-pair]
#pragma unroll
    for (int i = 0; i < 4; i++) { accP[i][0] = 0ull; accP[i][1] = 0ull; }

    {
        float4 ra0 = *reinterpret_cast<const float4*>(Ap0);
        float4 ra1 = *reinterpret_cast<const float4*>(Ap1);
        float4 rw0 = *reinterpret_cast<const float4*>(Wp0);
        float4 rw1 = *reinterpret_cast<const float4*>(Wp1);
        As[0][ak0 + 0][am0] = ra0.x;
        As[0][ak0 + 1][am0] = ra0.y;
        As[0][ak0 + 2][am0] = ra0.z;
        As[0][ak0 + 3][am0] = ra0.w;
        As[0][ak1 + 0][am1] = ra1.x;
        As[0][ak1 + 1][am1] = ra1.y;
        As[0][ak1 + 2][am1] = ra1.z;
        As[0][ak1 + 3][am1] = ra1.w;
        *reinterpret_cast<float4*>(&Ws[0][wk0][wn0]) = rw0;
        *reinterpret_cast<float4*>(&Ws[0][wk1][wn1]) = rw1;
    }
    __syncthreads();

    int buf = 0;
    for (int it = 0; it < nIters; it++) {
        const bool has_next = (it + 1) < nIters;
        float4 ra0, ra1, rw0, rw1;
        if (has_next) {
            const int ko = (it + 1) * 32;
            ra0 = *reinterpret_cast<const float4*>(Ap0 + ko);
            ra1 = *reinterpret_cast<const float4*>(Ap1 + ko);
            rw0 = *reinterpret_cast<const float4*>(Wp0 + (size_t)ko * N);
            rw1 = *reinterpret_cast<const float4*>(Wp1 + (size_t)ko * N);
        }
#pragma unroll
        for (int kk = 0; kk < 32; kk++) {
            float4 av = *reinterpret_cast<const float4*>(&As[buf][kk][ty * 4]);
            ulonglong2 wP = *reinterpret_cast<const ulonglong2*>(&Ws[buf][kk][tx * 4]);
            unsigned long long a0 = dupf(av.x);
            unsigned long long a1 = dupf(av.y);
            unsigned long long a2 = dupf(av.z);
            unsigned long long a3 = dupf(av.w);
            fma2(accP[0][0], a0, wP.x); fma2(accP[0][1], a0, wP.y);
            fma2(accP[1][0], a1, wP.x); fma2(accP[1][1], a1, wP.y);
            fma2(accP[2][0], a2, wP.x); fma2(accP[2][1], a2, wP.y);
            fma2(accP[3][0], a3, wP.x); fma2(accP[3][1], a3, wP.y);
        }
        if (has_next) {
            int nb = buf ^ 1;
            As[nb][ak0 + 0][am0] = ra0.x;
            As[nb][ak0 + 1][am0] = ra0.y;
            As[nb][ak0 + 2][am0] = ra0.z;
            As[nb][ak0 + 3][am0] = ra0.w;
            As[nb][ak1 + 0][am1] = ra1.x;
            As[nb][ak1 + 1][am1] = ra1.y;
            As[nb][ak1 + 2][am1] = ra1.z;
            As[nb][ak1 + 3][am1] = ra1.w;
            *reinterpret_cast<float4*>(&Ws[nb][wk0][wn0]) = rw0;
            *reinterpret_cast<float4*>(&Ws[nb][wk1][wn1]) = rw1;
            __syncthreads();
            buf = nb;
        }
    }

    float* P = g_part + (size_t)z * M * N;
#pragma unroll
    for (int i = 0; i < 4; i++) {
        int m = brow + ty * 4 + i;
        int n = bcol + tx * 4;
        float2 lo = unpk(accP[i][0]);
        float2 hi = unpk(accP[i][1]);
        float4 o;
        o.x = lo.x; o.y = lo.y; o.z = hi.x; o.w = hi.y;
        *reinterpret_cast<float4*>(&P[(size_t)m * N + n]) = o;
    }
}

// ---- split-K reductions ----
__global__ __launch_bounds__(256)
void reduce_l1(const float* __restrict__ b0, const float* __restrict__ b1) {
    const int MN = NN * HD1;
    int idx = blockIdx.x * 256 + threadIdx.x;
    if (idx < MN) {
        int n = idx & (HD1 - 1);
        g_xl1[idx] = g_part[idx] + g_part[idx + MN] + b0[n];
        g_xr1[idx] = g_part[idx + 2 * MN] + g_part[idx + 3 * MN] + b1[n];
    }
}
__global__ __launch_bounds__(256)
void reduce_l2(const float* __restrict__ b0, const float* __restrict__ b1) {
    const int MN = NN * HD2;
    int idx = blockIdx.x * 256 + threadIdx.x;
    if (idx < MN) {
        int n = idx & (HD2 - 1);
        float a = g_part[idx] + g_part[idx + MN] + g_part[idx + 2 * MN] + g_part[idx + 3 * MN];
        float b = g_part[idx + 4 * MN] + g_part[idx + 5 * MN] + g_part[idx + 6 * MN] + g_part[idx + 7 * MN];
        g_xl2[idx] = a + b0[n];
        g_xr2[idx] = b + b1[n];
    }
}

// ---- linear score terms: al[h,n] = att_h . xl_n, ar[h,n] = att_h . xr_n ----
template <int D>
__global__ __launch_bounds__(256)
void gat_lin(const float* __restrict__ xl, const float* __restrict__ xr,
             const float* __restrict__ att) {
    const int n = blockIdx.x;
    const int w = threadIdx.x >> 5, lane = threadIdx.x & 31;
    const int h = w >> 1;
    const int HD = NH * D;
    const float* src = (w & 1) ? xr : xl;
    float acc = 0.f;
    for (int k = lane; k < D; k += 32)
        acc = fmaf(att[h * D + k], src[(size_t)n * HD + h * D + k], acc);
#pragma unroll
    for (int o = 16; o; o >>= 1) acc += __shfl_xor_sync(0xffffffffu, acc, o);
    if (lane == 0) {
        if (w & 1) g_ar[h * NN + n] = acc;
        else       g_al[h * NN + n] = acc;
    }
}

// ---------------- GATv2 scores via abs identity ----------------
// lrelu(z,0.2) = 0.6 z + 0.4 |z|  =>
// s[h,i,j] = 0.6*(ar[h,i]+al[h,j]) + sum_d (0.4*att[h,d])*|xr+xl|
template <int D>
__global__ __launch_bounds__(256)
void gat_scores(const float* __restrict__ xl, const float* __restrict__ xr,
                const float* __restrict__ att, float* __restrict__ s_out) {
    const int HD = NH * D;
    const int j0 = blockIdx.x * 32;
    const int i0 = blockIdx.y * 32;
    const int h  = blockIdx.z;
    const int tid = threadIdx.x;
    const int tx = tid & 15, ty = tid >> 4;    // thread -> (2 i's, 2 j's)

    __shared__ __align__(8) float s_xr[64][34];
    __shared__ __align__(8) float s_xl[64][34];
    __shared__ float s_attf[D];

    for (int d = tid; d < D; d += 256) s_attf[d] = 0.4f * att[h * D + d];

    float a00 = 0.f, a01 = 0.f, a10 = 0.f, a11 = 0.f;

    for (int d0 = 0; d0 < D; d0 += 64) {
#pragma unroll
        for (int r = 0; r < 2; r++) {
            int idx = tid + r * 256;           // 0..511
            int row = idx >> 4;                // 0..31
            int kk  = (idx & 15) * 4;          // 0..60
            float4 vr = *reinterpret_cast<const float4*>(
                &xr[(size_t)(i0 + row) * HD + h * D + d0 + kk]);
            s_xr[kk + 0][row] = vr.x;
            s_xr[kk + 1][row] = vr.y;
            s_xr[kk + 2][row] = vr.z;
            s_xr[kk + 3][row] = vr.w;
            float4 vl = *reinterpret_cast<const float4*>(
                &xl[(size_t)(j0 + row) * HD + h * D + d0 + kk]);
            s_xl[kk + 0][row] = vl.x;
            s_xl[kk + 1][row] = vl.y;
            s_xl[kk + 2][row] = vl.z;
            s_xl[kk + 3][row] = vl.w;
        }
        __syncthreads();
#pragma unroll 16
        for (int kk = 0; kk < 64; kk++) {
            float attv = s_attf[d0 + kk];
            float2 xrP = *reinterpret_cast<const float2*>(&s_xr[kk][ty * 2]);
            float2 xlP = *reinterpret_cast<const float2*>(&s_xl[kk][tx * 2]);
            float z00 = xrP.x + xlP.x;
            float z01 = xrP.x + xlP.y;
            float z10 = xrP.y + xlP.x;
            float z11 = xrP.y + xlP.y;
            a00 = fmaf(attv, fabsf(z00), a00);
            a01 = fmaf(attv, fabsf(z01), a01);
            a10 = fmaf(attv, fabsf(z10), a10);
            a11 = fmaf(attv, fabsf(z11), a11);
        }
        __syncthreads();
    }

    float acc[2][2] = {{a00, a01}, {a10, a11}};
#pragma unroll
    for (int ii = 0; ii < 2; ii++) {
        int i = i0 + ty * 2 + ii;
        float ari = g_ar[h * NN + i];
#pragma unroll
        for (int jj = 0; jj < 2; jj++) {
            int j = j0 + tx * 2 + jj;
            float v = fmaf(0.6f, ari + g_al[h * NN + j], acc[ii][jj]);
            s_out[((size_t)h * NN + i) * NN + j] = (i == j) ? -INFINITY : v;
        }
    }
}

// ---------------- softmax over each (h,i) row of 256 ----------------
__global__ __launch_bounds__(256)
void gat_softmax(float* __restrict__ s) {
    float* row = s + (size_t)blockIdx.x * NN;
    const int tid = threadIdx.x, lane = tid & 31, w = tid >> 5;
    __shared__ float red[8];
    __shared__ float s_m, s_sum;

    float v = row[tid];
    float m = v;
#pragma unroll
    for (int o = 16; o; o >>= 1) m = fmaxf(m, __shfl_xor_sync(0xffffffffu, m, o));
    if (lane == 0) red[w] = m;
    __syncthreads();
    if (tid == 0) {
        float mm = red[0];
        for (int q = 1; q < 8; q++) mm = fmaxf(mm, red[q]);
        s_m = mm;
    }
    __syncthreads();
    float e = expf(v - s_m);
    float ss = e;
#pragma unroll
    for (int o = 16; o; o >>= 1) ss += __shfl_xor_sync(0xffffffffu, ss, o);
    if (lane == 0) red[w] = ss;
    __syncthreads();
    if (tid == 0) {
        float t = 0.f;
        for (int q = 0; q < 8; q++) t += red[q];
        s_sum = t;
    }
    __syncthreads();
    row[tid] = e * (1.f / s_sum);
}

// ------- aggregation GEMM per head: out[i, h*D+n] = sum_j a[h,i,j]*xl[j,h*D+n] ----
template <int D, int ACT>
__global__ __launch_bounds__(256)
void gat_agg(const float* __restrict__ a, const float* __restrict__ xl,
             const float* __restrict__ bias, float* __restrict__ out) {
    const int HD = NH * D;
    const int h = blockIdx.z;
    const int brow = blockIdx.y * 32;
    const int bcol = blockIdx.x * 64;
    const float* A = a + (size_t)h * NN * NN;
    const float* B = xl + h * D;

    __shared__ __align__(16) float As[2][32][36];
    __shared__ __align__(16) float Ws[2][32][64];

    const int tid = threadIdx.x;
    const int tx = tid & 15, ty = tid >> 4;

    const int aIdx = tid * 4;
    const int am = aIdx >> 5, ak = aIdx & 31;
    const int wIdx0 = tid * 4, wIdx1 = wIdx0 + 1024;
    const int wk0 = wIdx0 >> 6, wn0 = wIdx0 & 63;
    const int wk1 = wIdx1 >> 6, wn1 = wIdx1 & 63;

    const float* Ap  = A + (size_t)(brow + am) * NN + ak;
    const float* Bp0 = B + (size_t)wk0 * HD + bcol + wn0;
    const float* Bp1 = B + (size_t)wk1 * HD + bcol + wn1;

    unsigned long long accP[2][2];   // [i][j-pair]
    accP[0][0] = accP[0][1] = accP[1][0] = accP[1][1] = 0ull;

    {
        float4 ra  = *reinterpret_cast<const float4*>(Ap);
        float4 rw0 = *reinterpret_cast<const float4*>(Bp0);
        float4 rw1 = *reinterpret_cast<const float4*>(Bp1);
        As[0][ak + 0][am] = ra.x;
        As[0][ak + 1][am] = ra.y;
        As[0][ak + 2][am] = ra.z;
        As[0][ak + 3][am] = ra.w;
        *reinterpret_cast<float4*>(&Ws[0][wk0][wn0]) = rw0;
        *reinterpret_cast<float4*>(&Ws[0][wk1][wn1]) = rw1;
    }
    __syncthreads();

    int buf = 0;
    const int nIters = NN / 32;   // 8
    for (int it = 0; it < nIters; it++) {
        const bool has_next = (it + 1) < nIters;
        float4 ra, rw0, rw1;
        if (has_next) {
            const int ko = (it + 1) * 32;
            ra  = *reinterpret_cast<const float4*>(Ap + ko);
            rw0 = *reinterpret_cast<const float4*>(Bp0 + (size_t)ko * HD);
            rw1 = *reinterpret_cast<const float4*>(Bp1 + (size_t)ko * HD);
        }
#pragma unroll
        for (int kk = 0; kk < 32; kk++) {
            float2 av = *reinterpret_cast<const float2*>(&As[buf][kk][ty * 2]);
            ulonglong2 wP = *reinterpret_cast<const ulonglong2*>(&Ws[buf][kk][tx * 4]);
            unsigned long long a0 = dupf(av.x);
            unsigned long long a1 = dupf(av.y);
            fma2(accP[0][0], a0, wP.x); fma2(accP[0][1], a0, wP.y);
            fma2(accP[1][0], a1, wP.x); fma2(accP[1][1], a1, wP.y);
        }
        if (has_next) {
            int nb = buf ^ 1;
            As[nb][ak + 0][am] = ra.x;
            As[nb][ak + 1][am] = ra.y;
            As[nb][ak + 2][am] = ra.z;
            As[nb][ak + 3][am] = ra.w;
            *reinterpret_cast<float4*>(&Ws[nb][wk0][wn0]) = rw0;
            *reinterpret_cast<float4*>(&Ws[nb][wk1][wn1]) = rw1;
            __syncthreads();
            buf = nb;
        }
    }

    const int n = bcol + tx * 4;
    float4 bv = *reinterpret_cast<const float4*>(&bias[h * D + n]);
#pragma unroll
    for (int i = 0; i < 2; i++) {
        int m = brow + ty * 2 + i;
        float2 lo = unpk(accP[i][0]);
        float2 hi = unpk(accP[i][1]);
        float4 o;
        o.x = lo.x + bv.x;
        o.y = lo.y + bv.y;
        o.z = hi.x + bv.z;
        o.w = hi.y + bv.w;
        if (ACT == 1) {
            o.x = o.x > 0.f ? o.x : expm1f(o.x);
            o.y = o.y > 0.f ? o.y : expm1f(o.y);
            o.z = o.z > 0.f ? o.z : expm1f(o.z);
            o.w = o.w > 0.f ? o.w : expm1f(o.w);
        }
        *reinterpret_cast<float4*>(&out[(size_t)m * HD + h * D + n]) = o;
    }
}

// ------- LayerNorm + ReLU + residual, rows 0..127; sums Wout's 8 split-K partials
__global__ __launch_bounds__(256)
void ln_residual(const float* __restrict__ bout,
                 const float* __restrict__ ln_g, const float* __restrict__ ln_b,
                 const float* __restrict__ rw, float* __restrict__ out) {
    const int i = blockIdx.x;
    const int tid = threadIdx.x;
    const int lane = tid & 31, warp = tid >> 5;
    const int MN = 128 * FDIM;
    __shared__ float s_red1[8], s_red2[8];
    __shared__ float s_mu, s_rstd;

    float yv[4];
    float sum = 0.f, sq = 0.f;
#pragma unroll
    for (int q = 0; q < 4; q++) {
        int c = tid + q * 256;
        float v = bout[c];
#pragma unroll
        for (int s = 0; s < 8; s++)
            v += g_part[s * MN + i * FDIM + c];
        yv[q] = v;
        sum += v; sq += v * v;
    }
#pragma unroll
    for (int o = 16; o; o >>= 1) {
        sum += __shfl_xor_sync(0xffffffffu, sum, o);
        sq  += __shfl_xor_sync(0xffffffffu, sq,  o);
    }
    if (lane == 0) { s_red1[warp] = sum; s_red2[warp] = sq; }
    __syncthreads();
    if (tid == 0) {
        float ts = 0.f, tq = 0.f;
        for (int w = 0; w < 8; w++) { ts += s_red1[w]; tq += s_red2[w]; }
        float mu = ts / FDIM;
        float var = tq / FDIM - mu * mu;
        s_mu = mu;
        s_rstd = rsqrtf(var + 1e-5f);
    }
    __syncthreads();
    float mu = s_mu, rstd = s_rstd, w0 = rw[0];
#pragma unroll
    for (int q = 0; q < 4; q++) {
        int c = tid + q * 256;
        float v = (yv[q] - mu) * rstd * ln_g[c] + ln_b[c];
        v = fmaxf(v, 0.f);
        out[i * FDIM + c] = v + w0 * g_x[i * FDIM + c];
    }
}

// ---------------- launch ----------------
extern "C" void kernel_launch(void* const* d_in, const int* in_sizes, int n_in,
                              void* d_out, int out_size) {
    (void)in_sizes; (void)n_in; (void)out_size;
    const float* v1f   = (const float*)d_in[0];
    const float* v2f   = (const float*)d_in[1];
    const float* v1fu  = (const float*)d_in[2];
    const float* v2fu  = (const float*)d_in[3];
    const float* Wl1   = (const float*)d_in[4];
    const float* bl1   = (const float*)d_in[5];
    const float* Wr1   = (const float*)d_in[6];
    const float* br1   = (const float*)d_in[7];
    const float* att1  = (const float*)d_in[8];
    const float* bias1 = (const float*)d_in[9];
    const float* Wl2   = (const float*)d_in[10];
    const float* bl2   = (const float*)d_in[11];
    const float* Wr2   = (const float*)d_in[12];
    const float* br2   = (const float*)d_in[13];
    const float* att2  = (const float*)d_in[14];
    const float* bias2 = (const float*)d_in[15];
    const float* Wout  = (const float*)d_in[16];
    const float* bout  = (const float*)d_in[17];
    const float* ln_g  = (const float*)d_in[18];
    const float* ln_b  = (const float*)d_in[19];
    const float* rw    = (const float*)d_in[20];
    float* out = (float*)d_out;

    float *x, *xl1, *xr1, *o1, *xl2, *xr2, *o2, *sbuf;
    cudaGetSymbolAddress((void**)&x,   g_x);
    cudaGetSymbolAddress((void**)&xl1, g_xl1);
    cudaGetSymbolAddress((void**)&xr1, g_xr1);
    cudaGetSymbolAddress((void**)&o1,  g_o1);
    cudaGetSymbolAddress((void**)&xl2, g_xl2);
    cudaGetSymbolAddress((void**)&xr2, g_xr2);
    cudaGetSymbolAddress((void**)&o2,  g_o2);
    cudaGetSymbolAddress((void**)&sbuf, g_s);

    concat_kernel<<<(64 * FDIM + 255) / 256, 256>>>(v1f, v2f, v1fu, v2fu);

    // ---- GAT layer 1 linear: split-K=2 -> 512 CTAs
    {
        dim3 grid(HD1 / 64, NN / 64, 4);
        gemm_pipe<<<grid, 256>>>(x, Wl1, Wr1, NN, FDIM, HD1, 2);
    }
    reduce_l1<<<(NN * HD1 + 255) / 256, 256>>>(bl1, br1);

    // ---- GAT layer 1 attention
    gat_lin<HIDD><<<NN, 256>>>(xl1, xr1, att1);
    {
        dim3 grid(NN / 32, NN / 32, NH);
        gat_scores<HIDD><<<grid, 256>>>(xl1, xr1, att1, sbuf);
    }
    gat_softmax<<<NH * NN, 256>>>(sbuf);
    {
        dim3 grid(HIDD / 64, NN / 32, NH);
        gat_agg<HIDD, 1><<<grid, 256>>>(sbuf, xl1, bias1, o1);
    }

    // ---- GAT layer 2 linear: split-K=4 -> 512 CTAs
    {
        dim3 grid(HD2 / 64, NN / 64, 8);
        gemm_pipe<<<grid, 256>>>(o1, Wl2, Wr2, NN, HD1, HD2, 4);
    }
    reduce_l2<<<(NN * HD2 + 255) / 256, 256>>>(bl2, br2);

    // ---- GAT layer 2 attention
    gat_lin<DD2><<<NN, 256>>>(xl2, xr2, att2);
    {
        dim3 grid(NN / 32, NN / 32, NH);
        gat_scores<DD2><<<grid, 256>>>(xl2, xr2, att2, sbuf);
    }
    gat_softmax<<<NH * NN, 256>>>(sbuf);
    {
        dim3 grid(DD2 / 64, NN / 32, NH);
        gat_agg<DD2, 0><<<grid, 256>>>(sbuf, xl2, bias2, o2);
    }

    // ---- Output projection rows 0..127: split-K=8 -> 256 CTAs
    {
        dim3 grid(FDIM / 64, 128 / 64, 8);
        gemm_pipe<<<grid, 256>>>(o2, Wout, Wout, 128, FDIM, FDIM, 8);
    }
    ln_residual<<<128, 256>>>(bout, ln_g, ln_b, rw, out);
}

// round 7
// speedup vs baseline: 5.6228x; 1.2015x over previous
#include <cuda_runtime.h>
#include <math.h>

#define NN   256      // total graph nodes
#define FDIM 1024
#define HIDD 512
#define NH   4
#define DD2  256
#define HD1  2048     // NH*HIDD
#define HD2  1024     // NH*DD2

// ---- device scratch (no allocations allowed) ----
__device__ float g_x  [NN * FDIM];
__device__ float g_xl1[NN * HD1];
__device__ float g_xr1[NN * HD1];
__device__ float g_o1 [NN * HD1];
__device__ float g_xl2[NN * HD2];
__device__ float g_xr2[NN * HD2];
__device__ float g_o2 [NN * HD2];
__device__ float g_s  [NH * NN * NN];   // attention scores / weights
__device__ float g_al [NH * NN];        // att . xl per (head, node)
__device__ float g_part[1 << 21];       // 8 MB split-K partials

// ---- packed f32x2 helpers (FFMA2: ptxas never emits it, PTX-only path) ----
__device__ __forceinline__ unsigned long long dupf(float x) {
    unsigned long long r;
    asm("mov.b64 %0, {%1, %1};" : "=l"(r) : "f"(x));
    return r;
}
__device__ __forceinline__ void fma2(unsigned long long& acc,
                                     unsigned long long a, unsigned long long b) {
    asm("fma.rn.f32x2 %0, %1, %2, %0;" : "+l"(acc) : "l"(a), "l"(b));
}
__device__ __forceinline__ float2 unpk(unsigned long long v) {
    float2 r;
    asm("mov.b64 {%0, %1}, %2;" : "=f"(r.x), "=f"(r.y) : "l"(v));
    return r;
}

// ---------------- concat inputs into x [256,1024] ----------------
__global__ void concat_kernel(const float* __restrict__ a, const float* __restrict__ b,
                              const float* __restrict__ c, const float* __restrict__ d) {
    int idx = blockIdx.x * blockDim.x + threadIdx.x;
    if (idx < 64 * FDIM) {
        g_x[idx]              = a[idx];
        g_x[64  * FDIM + idx] = b[idx];
        g_x[128 * FDIM + idx] = c[idx];
        g_x[192 * FDIM + idx] = d[idx];
    }
}

// ------- pipelined fp32 GEMM, 128x64 tile, BK=16, split-K, dual-GEMM, FFMA2 -----
// A tile k-major: i-pairs natively packed for fma2 (no dup on A side).
// Writes partial to g_part + z*M*N. z = gemm_idx*splitk + split.
__global__ __launch_bounds__(256)
void gemm_pipe(const float* __restrict__ A,
               const float* __restrict__ W0, const float* __restrict__ W1,
               int M, int K, int N, int splitk) {
    const int z = blockIdx.z;
    const int g = z / splitk;
    const int s = z % splitk;
    const float* W = g ? W1 : W0;
    const int kspan = K / splitk;
    const int kbeg  = s * kspan;
    const int nIters = kspan / 16;

    __shared__ __align__(16) float As[2][16][132];   // k-major, 132*4B = 16B-mult
    __shared__ __align__(16) float Ws[2][16][64];

    const int brow = blockIdx.y * 128;
    const int bcol = blockIdx.x * 64;
    const int tid  = threadIdx.x;
    const int tx   = tid & 15;        // 4 cols at tx*4
    const int ty   = tid >> 4;        // 8 rows at ty*8

    // A: 128x16 = 2048 floats, 2 float4/thread
    const int am0 = tid >> 2;                 // 0..63
    const int ak0 = (tid & 3) * 4;            // 0,4,8,12
    const int am1 = am0 + 64;
    // W: 16x64 = 1024 floats, 1 float4/thread
    const int wk = tid >> 4;
    const int wn = (tid & 15) * 4;

    const float* Ap0 = A + (size_t)(brow + am0) * K + kbeg + ak0;
    const float* Ap1 = A + (size_t)(brow + am1) * K + kbeg + ak0;
    const float* Wp  = W + (size_t)(kbeg + wk) * N + bcol + wn;

    unsigned long long acc[4][4];   // [i-pair][j]
#pragma unroll
    for (int i = 0; i < 4; i++)
#pragma unroll
        for (int j = 0; j < 4; j++) acc[i][j] = 0ull;

    {
        float4 ra0 = *reinterpret_cast<const float4*>(Ap0);
        float4 ra1 = *reinterpret_cast<const float4*>(Ap1);
        float4 rw  = *reinterpret_cast<const float4*>(Wp);
        As[0][ak0 + 0][am0] = ra0.x;
        As[0][ak0 + 1][am0] = ra0.y;
        As[0][ak0 + 2][am0] = ra0.z;
        As[0][ak0 + 3][am0] = ra0.w;
        As[0][ak0 + 0][am1] = ra1.x;
        As[0][ak0 + 1][am1] = ra1.y;
        As[0][ak0 + 2][am1] = ra1.z;
        As[0][ak0 + 3][am1] = ra1.w;
        *reinterpret_cast<float4*>(&Ws[0][wk][wn]) = rw;
    }
    __syncthreads();

    int buf = 0;
    for (int it = 0; it < nIters; it++) {
        const bool has_next = (it + 1) < nIters;
        float4 ra0, ra1, rw;
        if (has_next) {
            const int ko = (it + 1) * 16;
            ra0 = *reinterpret_cast<const float4*>(Ap0 + ko);
            ra1 = *reinterpret_cast<const float4*>(Ap1 + ko);
            rw  = *reinterpret_cast<const float4*>(Wp + (size_t)ko * N);
        }
#pragma unroll
        for (int kk = 0; kk < 16; kk++) {
            ulonglong2 aP01 = *reinterpret_cast<const ulonglong2*>(&As[buf][kk][ty * 8]);
            ulonglong2 aP23 = *reinterpret_cast<const ulonglong2*>(&As[buf][kk][ty * 8 + 4]);
            float4 wv = *reinterpret_cast<const float4*>(&Ws[buf][kk][tx * 4]);
            unsigned long long w0 = dupf(wv.x);
            unsigned long long w1 = dupf(wv.y);
            unsigned long long w2 = dupf(wv.z);
            unsigned long long w3 = dupf(wv.w);
            fma2(acc[0][0], aP01.x, w0); fma2(acc[0][1], aP01.x, w1);
            fma2(acc[0][2], aP01.x, w2); fma2(acc[0][3], aP01.x, w3);
            fma2(acc[1][0], aP01.y, w0); fma2(acc[1][1], aP01.y, w1);
            fma2(acc[1][2], aP01.y, w2); fma2(acc[1][3], aP01.y, w3);
            fma2(acc[2][0], aP23.x, w0); fma2(acc[2][1], aP23.x, w1);
            fma2(acc[2][2], aP23.x, w2); fma2(acc[2][3], aP23.x, w3);
            fma2(acc[3][0], aP23.y, w0); fma2(acc[3][1], aP23.y, w1);
            fma2(acc[3][2], aP23.y, w2); fma2(acc[3][3], aP23.y, w3);
        }
        if (has_next) {
            int nb = buf ^ 1;
            As[nb][ak0 + 0][am0] = ra0.x;
            As[nb][ak0 + 1][am0] = ra0.y;
            As[nb][ak0 + 2][am0] = ra0.z;
            As[nb][ak0 + 3][am0] = ra0.w;
            As[nb][ak0 + 0][am1] = ra1.x;
            As[nb][ak0 + 1][am1] = ra1.y;
            As[nb][ak0 + 2][am1] = ra1.z;
            As[nb][ak0 + 3][am1] = ra1.w;
            *reinterpret_cast<float4*>(&Ws[nb][wk][wn]) = rw;
            __syncthreads();
            buf = nb;
        }
    }

    float* P = g_part + (size_t)z * M * N;
    const int n = bcol + tx * 4;
#pragma unroll
    for (int ip = 0; ip < 4; ip++) {
        float2 c0 = unpk(acc[ip][0]);
        float2 c1 = unpk(acc[ip][1]);
        float2 c2 = unpk(acc[ip][2]);
        float2 c3 = unpk(acc[ip][3]);
        int m0 = brow + ty * 8 + 2 * ip;
        float4 r0; r0.x = c0.x; r0.y = c1.x; r0.z = c2.x; r0.w = c3.x;
        float4 r1; r1.x = c0.y; r1.y = c1.y; r1.z = c2.y; r1.w = c3.y;
        *reinterpret_cast<float4*>(&P[(size_t)m0 * N + n])       = r0;
        *reinterpret_cast<float4*>(&P[(size_t)(m0 + 1) * N + n]) = r1;
    }
}

// ---- split-K reduce + bias + fused al = att.xl per (head, node) ----
// Layer 1: one CTA per node; thread covers 8 contiguous floats of the 2048-row.
__global__ __launch_bounds__(256)
void reduce_al1(const float* __restrict__ b0, const float* __restrict__ b1,
                const float* __restrict__ att) {
    const int n = blockIdx.x;
    const int tid = threadIdx.x;
    const int lane = tid & 31, w = tid >> 5;
    const int MN = NN * HD1;
    const size_t ro = (size_t)n * HD1;
    __shared__ float sred[8];

    float alp = 0.f;
#pragma unroll
    for (int q = 0; q < 2; q++) {
        int c = tid * 8 + q * 4;
        float4 p0 = *reinterpret_cast<const float4*>(&g_part[ro + c]);
        float4 p1 = *reinterpret_cast<const float4*>(&g_part[MN + ro + c]);
        float4 bb = *reinterpret_cast<const float4*>(&b0[c]);
        float4 v;
        v.x = p0.x + p1.x + bb.x;
        v.y = p0.y + p1.y + bb.y;
        v.z = p0.z + p1.z + bb.z;
        v.w = p0.w + p1.w + bb.w;
        *reinterpret_cast<float4*>(&g_xl1[ro + c]) = v;
        float4 at = *reinterpret_cast<const float4*>(&att[c]);
        alp = fmaf(at.x, v.x, alp);
        alp = fmaf(at.y, v.y, alp);
        alp = fmaf(at.z, v.z, alp);
        alp = fmaf(at.w, v.w, alp);

        float4 q0 = *reinterpret_cast<const float4*>(&g_part[2 * (size_t)MN + ro + c]);
        float4 q1 = *reinterpret_cast<const float4*>(&g_part[3 * (size_t)MN + ro + c]);
        float4 b2 = *reinterpret_cast<const float4*>(&b1[c]);
        float4 u;
        u.x = q0.x + q1.x + b2.x;
        u.y = q0.y + q1.y + b2.y;
        u.z = q0.z + q1.z + b2.z;
        u.w = q0.w + q1.w + b2.w;
        *reinterpret_cast<float4*>(&g_xr1[ro + c]) = u;
    }
#pragma unroll
    for (int o = 16; o; o >>= 1) alp += __shfl_xor_sync(0xffffffffu, alp, o);
    if (lane == 0) sred[w] = alp;
    __syncthreads();
    if (tid < 4) g_al[tid * NN + n] = sred[2 * tid] + sred[2 * tid + 1];
}

// Layer 2: splitk=4; thread covers 4 floats of the 1024-row.
__global__ __launch_bounds__(256)
void reduce_al2(const float* __restrict__ b0, const float* __restrict__ b1,
                const float* __restrict__ att) {
    const int n = blockIdx.x;
    const int tid = threadIdx.x;
    const int lane = tid & 31, w = tid >> 5;
    const int MN = NN * HD2;
    const size_t ro = (size_t)n * HD2;
    __shared__ float sred[8];

    int c = tid * 4;
    float4 p0 = *reinterpret_cast<const float4*>(&g_part[ro + c]);
    float4 p1 = *reinterpret_cast<const float4*>(&g_part[(size_t)MN + ro + c]);
    float4 p2 = *reinterpret_cast<const float4*>(&g_part[2 * (size_t)MN + ro + c]);
    float4 p3 = *reinterpret_cast<const float4*>(&g_part[3 * (size_t)MN + ro + c]);
    float4 bb = *reinterpret_cast<const float4*>(&b0[c]);
    float4 v;
    v.x = p0.x + p1.x + p2.x + p3.x + bb.x;
    v.y = p0.y + p1.y + p2.y + p3.y + bb.y;
    v.z = p0.z + p1.z + p2.z + p3.z + bb.z;
    v.w = p0.w + p1.w + p2.w + p3.w + bb.w;
    *reinterpret_cast<float4*>(&g_xl2[ro + c]) = v;
    float4 at = *reinterpret_cast<const float4*>(&att[c]);
    float alp = at.x * v.x + at.y * v.y + at.z * v.z + at.w * v.w;

    float4 q0 = *reinterpret_cast<const float4*>(&g_part[4 * (size_t)MN + ro + c]);
    float4 q1 = *reinterpret_cast<const float4*>(&g_part[5 * (size_t)MN + ro + c]);
    float4 q2 = *reinterpret_cast<const float4*>(&g_part[6 * (size_t)MN + ro + c]);
    float4 q3 = *reinterpret_cast<const float4*>(&g_part[7 * (size_t)MN + ro + c]);
    float4 b2 = *reinterpret_cast<const float4*>(&b1[c]);
    float4 u;
    u.x = q0.x + q1.x + q2.x + q3.x + b2.x;
    u.y = q0.y + q1.y + q2.y + q3.y + b2.y;
    u.z = q0.z + q1.z + q2.z + q3.z + b2.z;
    u.w = q0.w + q1.w + q2.w + q3.w + b2.w;
    *reinterpret_cast<float4*>(&g_xr2[ro + c]) = u;

#pragma unroll
    for (int o = 16; o; o >>= 1) alp += __shfl_xor_sync(0xffffffffu, alp, o);
    if (lane == 0) sred[w] = alp;
    __syncthreads();
    if (tid < 4) g_al[tid * NN + n] = sred[2 * tid] + sred[2 * tid + 1];
}

// ---------------- GATv2 scores via abs identity ----------------
// lrelu(z,0.2) = 0.6 z + 0.4 |z|. The 0.6*ar_i term is row-constant and cancels
// in softmax, so: s[h,i,j] = 0.6*al[h,j] + sum_d (0.4*att[h,d])*|xr_i+xl_j|
template <int D>
__global__ __launch_bounds__(256)
void gat_scores(const float* __restrict__ xl, const float* __restrict__ xr,
                const float* __restrict__ att, float* __restrict__ s_out) {
    const int HD = NH * D;
    const int j0 = blockIdx.x * 32;
    const int i0 = blockIdx.y * 32;
    const int h  = blockIdx.z;
    const int tid = threadIdx.x;
    const int tx = tid & 15, ty = tid >> 4;    // thread -> (2 i's, 2 j's)

    __shared__ __align__(8) float s_xr[64][34];
    __shared__ __align__(8) float s_xl[64][34];
    __shared__ float s_attf[D];

    for (int d = tid; d < D; d += 256) s_attf[d] = 0.4f * att[h * D + d];

    float a00 = 0.f, a01 = 0.f, a10 = 0.f, a11 = 0.f;

    for (int d0 = 0; d0 < D; d0 += 64) {
#pragma unroll
        for (int r = 0; r < 2; r++) {
            int idx = tid + r * 256;           // 0..511
            int row = idx >> 4;                // 0..31
            int kk  = (idx & 15) * 4;          // 0..60
            float4 vr = *reinterpret_cast<const float4*>(
                &xr[(size_t)(i0 + row) * HD + h * D + d0 + kk]);
            s_xr[kk + 0][row] = vr.x;
            s_xr[kk + 1][row] = vr.y;
            s_xr[kk + 2][row] = vr.z;
            s_xr[kk + 3][row] = vr.w;
            float4 vl = *reinterpret_cast<const float4*>(
                &xl[(size_t)(j0 + row) * HD + h * D + d0 + kk]);
            s_xl[kk + 0][row] = vl.x;
            s_xl[kk + 1][row] = vl.y;
            s_xl[kk + 2][row] = vl.z;
            s_xl[kk + 3][row] = vl.w;
        }
        __syncthreads();
#pragma unroll 16
        for (int kk = 0; kk < 64; kk++) {
            float attv = s_attf[d0 + kk];
            float2 xrP = *reinterpret_cast<const float2*>(&s_xr[kk][ty * 2]);
            float2 xlP = *reinterpret_cast<const float2*>(&s_xl[kk][tx * 2]);
            float z00 = xrP.x + xlP.x;
            float z01 = xrP.x + xlP.y;
            float z10 = xrP.y + xlP.x;
            float z11 = xrP.y + xlP.y;
            a00 = fmaf(attv, fabsf(z00), a00);
            a01 = fmaf(attv, fabsf(z01), a01);
            a10 = fmaf(attv, fabsf(z10), a10);
            a11 = fmaf(attv, fabsf(z11), a11);
        }
        __syncthreads();
    }

    float acc[2][2] = {{a00, a01}, {a10, a11}};
#pragma unroll
    for (int ii = 0; ii < 2; ii++) {
        int i = i0 + ty * 2 + ii;
#pragma unroll
        for (int jj = 0; jj < 2; jj++) {
            int j = j0 + tx * 2 + jj;
            float v = fmaf(0.6f, g_al[h * NN + j], acc[ii][jj]);
            s_out[((size_t)h * NN + i) * NN + j] = (i == j) ? -INFINITY : v;
        }
    }
}

// ---------------- softmax over each (h,i) row of 256 ----------------
__global__ __launch_bounds__(256)
void gat_softmax(float* __restrict__ s) {
    float* row = s + (size_t)blockIdx.x * NN;
    const int tid = threadIdx.x, lane = tid & 31, w = tid >> 5;
    __shared__ float red[8];
    __shared__ float s_m, s_sum;

    float v = row[tid];
    float m = v;
#pragma unroll
    for (int o = 16; o; o >>= 1) m = fmaxf(m, __shfl_xor_sync(0xffffffffu, m, o));
    if (lane == 0) red[w] = m;
    __syncthreads();
    if (tid == 0) {
        float mm = red[0];
        for (int q = 1; q < 8; q++) mm = fmaxf(mm, red[q]);
        s_m = mm;
    }
    __syncthreads();
    float e = expf(v - s_m);
    float ss = e;
#pragma unroll
    for (int o = 16; o; o >>= 1) ss += __shfl_xor_sync(0xffffffffu, ss, o);
    if (lane == 0) red[w] = ss;
    __syncthreads();
    if (tid == 0) {
        float t = 0.f;
        for (int q = 0; q < 8; q++) t += red[q];
        s_sum = t;
    }
    __syncthreads();
    row[tid] = e * (1.f / s_sum);
}

// ------- aggregation GEMM per head: out[i, h*D+n] = sum_j a[h,i,j]*xl[j,h*D+n] ----
template <int D, int ACT>
__global__ __launch_bounds__(256)
void gat_agg(const float* __restrict__ a, const float* __restrict__ xl,
             const float* __restrict__ bias, float* __restrict__ out) {
    const int HD = NH * D;
    const int h = blockIdx.z;
    const int brow = blockIdx.y * 32;
    const int bcol = blockIdx.x * 64;
    const float* A = a + (size_t)h * NN * NN;
    const float* B = xl + h * D;

    __shared__ __align__(16) float As[2][32][36];
    __shared__ __align__(16) float Ws[2][32][64];

    const int tid = threadIdx.x;
    const int tx = tid & 15, ty = tid >> 4;

    const int aIdx = tid * 4;
    const int am = aIdx >> 5, ak = aIdx & 31;
    const int wIdx0 = tid * 4, wIdx1 = wIdx0 + 1024;
    const int wk0 = wIdx0 >> 6, wn0 = wIdx0 & 63;
    const int wk1 = wIdx1 >> 6, wn1 = wIdx1 & 63;

    const float* Ap  = A + (size_t)(brow + am) * NN + ak;
    const float* Bp0 = B + (size_t)wk0 * HD + bcol + wn0;
    const float* Bp1 = B + (size_t)wk1 * HD + bcol + wn1;

    unsigned long long accP[2][2];   // [i][j-pair]
    accP[0][0] = accP[0][1] = accP[1][0] = accP[1][1] = 0ull;

    {
        float4 ra  = *reinterpret_cast<const float4*>(Ap);
        float4 rw0 = *reinterpret_cast<const float4*>(Bp0);
        float4 rw1 = *reinterpret_cast<const float4*>(Bp1);
        As[0][ak + 0][am] = ra.x;
        As[0][ak + 1][am] = ra.y;
        As[0][ak + 2][am] = ra.z;
        As[0][ak + 3][am] = ra.w;
        *reinterpret_cast<float4*>(&Ws[0][wk0][wn0]) = rw0;
        *reinterpret_cast<float4*>(&Ws[0][wk1][wn1]) = rw1;
    }
    __syncthreads();

    int buf = 0;
    const int nIters = NN / 32;   // 8
    for (int it = 0; it < nIters; it++) {
        const bool has_next = (it + 1) < nIters;
        float4 ra, rw0, rw1;
        if (has_next) {
            const int ko = (it + 1) * 32;
            ra  = *reinterpret_cast<const float4*>(Ap + ko);
            rw0 = *reinterpret_cast<const float4*>(Bp0 + (size_t)ko * HD);
            rw1 = *reinterpret_cast<const float4*>(Bp1 + (size_t)ko * HD);
        }
#pragma unroll
        for (int kk = 0; kk < 32; kk++) {
            float2 av = *reinterpret_cast<const float2*>(&As[buf][kk][ty * 2]);
            ulonglong2 wP = *reinterpret_cast<const ulonglong2*>(&Ws[buf][kk][tx * 4]);
            unsigned long long a0 = dupf(av.x);
            unsigned long long a1 = dupf(av.y);
            fma2(accP[0][0], a0, wP.x); fma2(accP[0][1], a0, wP.y);
            fma2(accP[1][0], a1, wP.x); fma2(accP[1][1], a1, wP.y);
        }
        if (has_next) {
            int nb = buf ^ 1;
            As[nb][ak + 0][am] = ra.x;
            As[nb][ak + 1][am] = ra.y;
            As[nb][ak + 2][am] = ra.z;
            As[nb][ak + 3][am] = ra.w;
            *reinterpret_cast<float4*>(&Ws[nb][wk0][wn0]) = rw0;
            *reinterpret_cast<float4*>(&Ws[nb][wk1][wn1]) = rw1;
            __syncthreads();
            buf = nb;
        }
    }

    const int n = bcol + tx * 4;
    float4 bv = *reinterpret_cast<const float4*>(&bias[h * D + n]);
#pragma unroll
    for (int i = 0; i < 2; i++) {
        int m = brow + ty * 2 + i;
        float2 lo = unpk(accP[i][0]);
        float2 hi = unpk(accP[i][1]);
        float4 o;
        o.x = lo.x + bv.x;
        o.y = lo.y + bv.y;
        o.z = hi.x + bv.z;
        o.w = hi.y + bv.w;
        if (ACT == 1) {
            o.x = o.x > 0.f ? o.x : expm1f(o.x);
            o.y = o.y > 0.f ? o.y : expm1f(o.y);
            o.z = o.z > 0.f ? o.z : expm1f(o.z);
            o.w = o.w > 0.f ? o.w : expm1f(o.w);
        }
        *reinterpret_cast<float4*>(&out[(size_t)m * HD + h * D + n]) = o;
    }
}

// ------- LayerNorm + ReLU + residual, rows 0..127; sums Wout's 16 split-K partials
__global__ __launch_bounds__(256)
void ln_residual(const float* __restrict__ bout,
                 const float* __restrict__ ln_g, const float* __restrict__ ln_b,
                 const float* __restrict__ rw, float* __restrict__ out) {
    const int i = blockIdx.x;
    const int tid = threadIdx.x;
    const int lane = tid & 31, warp = tid >> 5;
    const int MN = 128 * FDIM;
    __shared__ float s_red1[8], s_red2[8];
    __shared__ float s_mu, s_rstd;

    float yv[4];
    float sum = 0.f, sq = 0.f;
#pragma unroll
    for (int q = 0; q < 4; q++) {
        int c = tid + q * 256;
        float v = bout[c];
#pragma unroll
        for (int s = 0; s < 16; s++)
            v += g_part[(size_t)s * MN + i * FDIM + c];
        yv[q] = v;
        sum += v; sq += v * v;
    }
#pragma unroll
    for (int o = 16; o; o >>= 1) {
        sum += __shfl_xor_sync(0xffffffffu, sum, o);
        sq  += __shfl_xor_sync(0xffffffffu, sq,  o);
    }
    if (lane == 0) { s_red1[warp] = sum; s_red2[warp] = sq; }
    __syncthreads();
    if (tid == 0) {
        float ts = 0.f, tq = 0.f;
        for (int w = 0; w < 8; w++) { ts += s_red1[w]; tq += s_red2[w]; }
        float mu = ts / FDIM;
        float var = tq / FDIM - mu * mu;
        s_mu = mu;
        s_rstd = rsqrtf(var + 1e-5f);
    }
    __syncthreads();
    float mu = s_mu, rstd = s_rstd, w0 = rw[0];
#pragma unroll
    for (int q = 0; q < 4; q++) {
        int c = tid + q * 256;
        float v = (yv[q] - mu) * rstd * ln_g[c] + ln_b[c];
        v = fmaxf(v, 0.f);
        out[i * FDIM + c] = v + w0 * g_x[i * FDIM + c];
    }
}

// ---------------- launch ----------------
extern "C" void kernel_launch(void* const* d_in, const int* in_sizes, int n_in,
                              void* d_out, int out_size) {
    (void)in_sizes; (void)n_in; (void)out_size;
    const float* v1f   = (const float*)d_in[0];
    const float* v2f   = (const float*)d_in[1];
    const float* v1fu  = (const float*)d_in[2];
    const float* v2fu  = (const float*)d_in[3];
    const float* Wl1   = (const float*)d_in[4];
    const float* bl1   = (const float*)d_in[5];
    const float* Wr1   = (const float*)d_in[6];
    const float* br1   = (const float*)d_in[7];
    const float* att1  = (const float*)d_in[8];
    const float* bias1 = (const float*)d_in[9];
    const float* Wl2   = (const float*)d_in[10];
    const float* bl2   = (const float*)d_in[11];
    const float* Wr2   = (const float*)d_in[12];
    const float* br2   = (const float*)d_in[13];
    const float* att2  = (const float*)d_in[14];
    const float* bias2 = (const float*)d_in[15];
    const float* Wout  = (const float*)d_in[16];
    const float* bout  = (const float*)d_in[17];
    const float* ln_g  = (const float*)d_in[18];
    const float* ln_b  = (const float*)d_in[19];
    const float* rw    = (const float*)d_in[20];
    float* out = (float*)d_out;

    float *x, *xl1, *xr1, *o1, *xl2, *xr2, *o2, *sbuf;
    cudaGetSymbolAddress((void**)&x,   g_x);
    cudaGetSymbolAddress((void**)&xl1, g_xl1);
    cudaGetSymbolAddress((void**)&xr1, g_xr1);
    cudaGetSymbolAddress((void**)&o1,  g_o1);
    cudaGetSymbolAddress((void**)&xl2, g_xl2);
    cudaGetSymbolAddress((void**)&xr2, g_xr2);
    cudaGetSymbolAddress((void**)&o2,  g_o2);
    cudaGetSymbolAddress((void**)&sbuf, g_s);

    concat_kernel<<<(64 * FDIM + 255) / 256, 256>>>(v1f, v2f, v1fu, v2fu);

    // ---- GAT layer 1 linear: split-K=2 -> 256 CTAs
    {
        dim3 grid(HD1 / 64, NN / 128, 4);
        gemm_pipe<<<grid, 256>>>(x, Wl1, Wr1, NN, FDIM, HD1, 2);
    }
    reduce_al1<<<NN, 256>>>(bl1, br1, att1);

    // ---- GAT layer 1 attention
    {
        dim3 grid(NN / 32, NN / 32, NH);
        gat_scores<HIDD><<<grid, 256>>>(xl1, xr1, att1, sbuf);
    }
    gat_softmax<<<NH * NN, 256>>>(sbuf);
    {
        dim3 grid(HIDD / 64, NN / 32, NH);
        gat_agg<HIDD, 1><<<grid, 256>>>(sbuf, xl1, bias1, o1);
    }

    // ---- GAT layer 2 linear: split-K=4 -> 256 CTAs
    {
        dim3 grid(HD2 / 64, NN / 128, 8);
        gemm_pipe<<<grid, 256>>>(o1, Wl2, Wr2, NN, HD1, HD2, 4);
    }
    reduce_al2<<<NN, 256>>>(bl2, br2, att2);

    // ---- GAT layer 2 attention
    {
        dim3 grid(NN / 32, NN / 32, NH);
        gat_scores<DD2><<<grid, 256>>>(xl2, xr2, att2, sbuf);
    }
    gat_softmax<<<NH * NN, 256>>>(sbuf);
    {
        dim3 grid(DD2 / 64, NN / 32, NH);
        gat_agg<DD2, 0><<<grid, 256>>>(sbuf, xl2, bias2, o2);
    }

    // ---- Output projection rows 0..127: split-K=16 -> 256 CTAs
    {
        dim3 grid(FDIM / 64, 1, 16);
        gemm_pipe<<<grid, 256>>>(o2, Wout, Wout, 128, FDIM, FDIM, 16);
    }
    ln_residual<<<128, 256>>>(bout, ln_g, ln_b, rw, out);
}

// round 8
// speedup vs baseline: 5.8720x; 1.0443x over previous
#include <cuda_runtime.h>
#include <math.h>

#define NN   256      // total graph nodes
#define FDIM 1024
#define HIDD 512
#define NH   4
#define DD2  256
#define HD1  2048     // NH*HIDD
#define HD2  1024     // NH*DD2

// ---- device scratch (no allocations allowed) ----
__device__ float g_xl1[NN * HD1];
__device__ float g_xr1[NN * HD1];
__device__ float g_o1 [NN * HD1];
__device__ float g_xl2[NN * HD2];
__device__ float g_xr2[NN * HD2];
__device__ float g_o2 [NN * HD2];
__device__ float g_s  [NH * NN * NN];   // attention scores / weights
__device__ float g_al [NH * NN];        // att . xl per (head, node)
__device__ float g_part[1 << 21];       // 8 MB split-K partials

// ---- packed f32x2 helpers (FFMA2: ptxas never emits it, PTX-only path) ----
__device__ __forceinline__ unsigned long long dupf(float x) {
    unsigned long long r;
    asm("mov.b64 %0, {%1, %1};" : "=l"(r) : "f"(x));
    return r;
}
__device__ __forceinline__ void fma2(unsigned long long& acc,
                                     unsigned long long a, unsigned long long b) {
    asm("fma.rn.f32x2 %0, %1, %2, %0;" : "+l"(acc) : "l"(a), "l"(b));
}
__device__ __forceinline__ float2 unpk(unsigned long long v) {
    float2 r;
    asm("mov.b64 {%0, %1}, %2;" : "=f"(r.x), "=f"(r.y) : "l"(v));
    return r;
}

// ------- pipelined fp32 GEMM, 128x64 tile, BK=16, split-K, dual-GEMM, FFMA2 -----
// If fromInputs != 0, A row r is read from the 4 concatenated inputs (64 rows each).
__global__ __launch_bounds__(256)
void gemm_pipe(const float* __restrict__ A,
               const float* __restrict__ I0, const float* __restrict__ I1,
               const float* __restrict__ I2, const float* __restrict__ I3,
               const float* __restrict__ W0, const float* __restrict__ W1,
               int M, int K, int N, int splitk, int fromInputs) {
    const int z = blockIdx.z;
    const int g = z / splitk;
    const int s = z % splitk;
    const float* W = g ? W1 : W0;
    const int kspan = K / splitk;
    const int kbeg  = s * kspan;
    const int nIters = kspan / 16;

    __shared__ __align__(16) float As[2][16][132];
    __shared__ __align__(16) float Ws[2][16][64];

    const int brow = blockIdx.y * 128;
    const int bcol = blockIdx.x * 64;
    const int tid  = threadIdx.x;
    const int tx   = tid & 15;        // 4 cols at tx*4
    const int ty   = tid >> 4;        // 8 rows at ty*8

    const int am0 = tid >> 2;                 // 0..63
    const int ak0 = (tid & 3) * 4;            // 0,4,8,12
    const int am1 = am0 + 64;
    const int wk = tid >> 4;
    const int wn = (tid & 15) * 4;

    const int r0 = brow + am0, r1 = brow + am1;
    const float* Ap0;
    const float* Ap1;
    if (fromInputs) {
        const float* b0 = (r0 < 64) ? I0 : (r0 < 128) ? I1 : (r0 < 192) ? I2 : I3;
        const float* b1 = (r1 < 64) ? I0 : (r1 < 128) ? I1 : (r1 < 192) ? I2 : I3;
        Ap0 = b0 + (size_t)(r0 & 63) * K + kbeg + ak0;
        Ap1 = b1 + (size_t)(r1 & 63) * K + kbeg + ak0;
    } else {
        Ap0 = A + (size_t)r0 * K + kbeg + ak0;
        Ap1 = A + (size_t)r1 * K + kbeg + ak0;
    }
    const float* Wp = W + (size_t)(kbeg + wk) * N + bcol + wn;

    unsigned long long acc[4][4];   // [i-pair][j]
#pragma unroll
    for (int i = 0; i < 4; i++)
#pragma unroll
        for (int j = 0; j < 4; j++) acc[i][j] = 0ull;

    {
        float4 ra0 = *reinterpret_cast<const float4*>(Ap0);
        float4 ra1 = *reinterpret_cast<const float4*>(Ap1);
        float4 rw  = *reinterpret_cast<const float4*>(Wp);
        As[0][ak0 + 0][am0] = ra0.x;
        As[0][ak0 + 1][am0] = ra0.y;
        As[0][ak0 + 2][am0] = ra0.z;
        As[0][ak0 + 3][am0] = ra0.w;
        As[0][ak0 + 0][am1] = ra1.x;
        As[0][ak0 + 1][am1] = ra1.y;
        As[0][ak0 + 2][am1] = ra1.z;
        As[0][ak0 + 3][am1] = ra1.w;
        *reinterpret_cast<float4*>(&Ws[0][wk][wn]) = rw;
    }
    __syncthreads();

    int buf = 0;
    for (int it = 0; it < nIters; it++) {
        const bool has_next = (it + 1) < nIters;
        float4 ra0, ra1, rw;
        if (has_next) {
            const int ko = (it + 1) * 16;
            ra0 = *reinterpret_cast<const float4*>(Ap0 + ko);
            ra1 = *reinterpret_cast<const float4*>(Ap1 + ko);
            rw  = *reinterpret_cast<const float4*>(Wp + (size_t)ko * N);
        }
#pragma unroll
        for (int kk = 0; kk < 16; kk++) {
            ulonglong2 aP01 = *reinterpret_cast<const ulonglong2*>(&As[buf][kk][ty * 8]);
            ulonglong2 aP23 = *reinterpret_cast<const ulonglong2*>(&As[buf][kk][ty * 8 + 4]);
            float4 wv = *reinterpret_cast<const float4*>(&Ws[buf][kk][tx * 4]);
            unsigned long long w0 = dupf(wv.x);
            unsigned long long w1 = dupf(wv.y);
            unsigned long long w2 = dupf(wv.z);
            unsigned long long w3 = dupf(wv.w);
            fma2(acc[0][0], aP01.x, w0); fma2(acc[0][1], aP01.x, w1);
            fma2(acc[0][2], aP01.x, w2); fma2(acc[0][3], aP01.x, w3);
            fma2(acc[1][0], aP01.y, w0); fma2(acc[1][1], aP01.y, w1);
            fma2(acc[1][2], aP01.y, w2); fma2(acc[1][3], aP01.y, w3);
            fma2(acc[2][0], aP23.x, w0); fma2(acc[2][1], aP23.x, w1);
            fma2(acc[2][2], aP23.x, w2); fma2(acc[2][3], aP23.x, w3);
            fma2(acc[3][0], aP23.y, w0); fma2(acc[3][1], aP23.y, w1);
            fma2(acc[3][2], aP23.y, w2); fma2(acc[3][3], aP23.y, w3);
        }
        if (has_next) {
            int nb = buf ^ 1;
            As[nb][ak0 + 0][am0] = ra0.x;
            As[nb][ak0 + 1][am0] = ra0.y;
            As[nb][ak0 + 2][am0] = ra0.z;
            As[nb][ak0 + 3][am0] = ra0.w;
            As[nb][ak0 + 0][am1] = ra1.x;
            As[nb][ak0 + 1][am1] = ra1.y;
            As[nb][ak0 + 2][am1] = ra1.z;
            As[nb][ak0 + 3][am1] = ra1.w;
            *reinterpret_cast<float4*>(&Ws[nb][wk][wn]) = rw;
            __syncthreads();
            buf = nb;
        }
    }

    float* P = g_part + (size_t)z * M * N;
    const int n = bcol + tx * 4;
#pragma unroll
    for (int ip = 0; ip < 4; ip++) {
        float2 c0 = unpk(acc[ip][0]);
        float2 c1 = unpk(acc[ip][1]);
        float2 c2 = unpk(acc[ip][2]);
        float2 c3 = unpk(acc[ip][3]);
        int m0 = brow + ty * 8 + 2 * ip;
        float4 rr0; rr0.x = c0.x; rr0.y = c1.x; rr0.z = c2.x; rr0.w = c3.x;
        float4 rr1; rr1.x = c0.y; rr1.y = c1.y; rr1.z = c2.y; rr1.w = c3.y;
        *reinterpret_cast<float4*>(&P[(size_t)m0 * N + n])       = rr0;
        *reinterpret_cast<float4*>(&P[(size_t)(m0 + 1) * N + n]) = rr1;
    }
}

// ---- split-K reduce + bias + fused al = att.xl per (head, node) ----
__global__ __launch_bounds__(256)
void reduce_al1(const float* __restrict__ b0, const float* __restrict__ b1,
                const float* __restrict__ att) {
    const int n = blockIdx.x;
    const int tid = threadIdx.x;
    const int lane = tid & 31, w = tid >> 5;
    const int MN = NN * HD1;
    const size_t ro = (size_t)n * HD1;
    __shared__ float sred[8];

    float alp = 0.f;
#pragma unroll
    for (int q = 0; q < 2; q++) {
        int c = tid * 8 + q * 4;
        float4 p0 = *reinterpret_cast<const float4*>(&g_part[ro + c]);
        float4 p1 = *reinterpret_cast<const float4*>(&g_part[MN + ro + c]);
        float4 bb = *reinterpret_cast<const float4*>(&b0[c]);
        float4 v;
        v.x = p0.x + p1.x + bb.x;
        v.y = p0.y + p1.y + bb.y;
        v.z = p0.z + p1.z + bb.z;
        v.w = p0.w + p1.w + bb.w;
        *reinterpret_cast<float4*>(&g_xl1[ro + c]) = v;
        float4 at = *reinterpret_cast<const float4*>(&att[c]);
        alp = fmaf(at.x, v.x, alp);
        alp = fmaf(at.y, v.y, alp);
        alp = fmaf(at.z, v.z, alp);
        alp = fmaf(at.w, v.w, alp);

        float4 q0 = *reinterpret_cast<const float4*>(&g_part[2 * (size_t)MN + ro + c]);
        float4 q1 = *reinterpret_cast<const float4*>(&g_part[3 * (size_t)MN + ro + c]);
        float4 b2 = *reinterpret_cast<const float4*>(&b1[c]);
        float4 u;
        u.x = q0.x + q1.x + b2.x;
        u.y = q0.y + q1.y + b2.y;
        u.z = q0.z + q1.z + b2.z;
        u.w = q0.w + q1.w + b2.w;
        *reinterpret_cast<float4*>(&g_xr1[ro + c]) = u;
    }
#pragma unroll
    for (int o = 16; o; o >>= 1) alp += __shfl_xor_sync(0xffffffffu, alp, o);
    if (lane == 0) sred[w] = alp;
    __syncthreads();
    if (tid < 4) g_al[tid * NN + n] = sred[2 * tid] + sred[2 * tid + 1];
}

__global__ __launch_bounds__(256)
void reduce_al2(const float* __restrict__ b0, const float* __restrict__ b1,
                const float* __restrict__ att) {
    const int n = blockIdx.x;
    const int tid = threadIdx.x;
    const int lane = tid & 31, w = tid >> 5;
    const int MN = NN * HD2;
    const size_t ro = (size_t)n * HD2;
    __shared__ float sred[8];

    int c = tid * 4;
    float4 p0 = *reinterpret_cast<const float4*>(&g_part[ro + c]);
    float4 p1 = *reinterpret_cast<const float4*>(&g_part[(size_t)MN + ro + c]);
    float4 p2 = *reinterpret_cast<const float4*>(&g_part[2 * (size_t)MN + ro + c]);
    float4 p3 = *reinterpret_cast<const float4*>(&g_part[3 * (size_t)MN + ro + c]);
    float4 bb = *reinterpret_cast<const float4*>(&b0[c]);
    float4 v;
    v.x = p0.x + p1.x + p2.x + p3.x + bb.x;
    v.y = p0.y + p1.y + p2.y + p3.y + bb.y;
    v.z = p0.z + p1.z + p2.z + p3.z + bb.z;
    v.w = p0.w + p1.w + p2.w + p3.w + bb.w;
    *reinterpret_cast<float4*>(&g_xl2[ro + c]) = v;
    float4 at = *reinterpret_cast<const float4*>(&att[c]);
    float alp = at.x * v.x + at.y * v.y + at.z * v.z + at.w * v.w;

    float4 q0 = *reinterpret_cast<const float4*>(&g_part[4 * (size_t)MN + ro + c]);
    float4 q1 = *reinterpret_cast<const float4*>(&g_part[5 * (size_t)MN + ro + c]);
    float4 q2 = *reinterpret_cast<const float4*>(&g_part[6 * (size_t)MN + ro + c]);
    float4 q3 = *reinterpret_cast<const float4*>(&g_part[7 * (size_t)MN + ro + c]);
    float4 b2 = *reinterpret_cast<const float4*>(&b1[c]);
    float4 u;
    u.x = q0.x + q1.x + q2.x + q3.x + b2.x;
    u.y = q0.y + q1.y + q2.y + q3.y + b2.y;
    u.z = q0.z + q1.z + q2.z + q3.z + b2.z;
    u.w = q0.w + q1.w + q2.w + q3.w + b2.w;
    *reinterpret_cast<float4*>(&g_xr2[ro + c]) = u;

#pragma unroll
    for (int o = 16; o; o >>= 1) alp += __shfl_xor_sync(0xffffffffu, alp, o);
    if (lane == 0) sred[w] = alp;
    __syncthreads();
    if (tid < 4) g_al[tid * NN + n] = sred[2 * tid] + sred[2 * tid + 1];
}

// ---------------- GATv2 scores via abs identity: 32i x 64j tile ----------------
// lrelu(z,0.2) = 0.6 z + 0.4 |z|; the 0.6*ar_i term cancels in softmax.
// s[h,i,j] = 0.6*al[h,j] + sum_d (0.4*att[h,d])*|xr_i+xl_j|
template <int D>
__global__ __launch_bounds__(256)
void gat_scores(const float* __restrict__ xl, const float* __restrict__ xr,
                const float* __restrict__ att, float* __restrict__ s_out) {
    const int HD = NH * D;
    const int j0 = blockIdx.x * 64;
    const int i0 = blockIdx.y * 32;
    const int h  = blockIdx.z;
    const int tid = threadIdx.x;
    const int tx = tid & 15, ty = tid >> 4;    // thread -> 2 i's (ty*2), 4 j's (tx*4)

    __shared__ __align__(16) float s_xr[64][34];   // [d][i]
    __shared__ __align__(16) float s_xl[64][68];   // [d][j]
    __shared__ float s_attf[D];

    for (int d = tid; d < D; d += 256) s_attf[d] = 0.4f * att[h * D + d];

    float acc[2][4] = {{0.f, 0.f, 0.f, 0.f}, {0.f, 0.f, 0.f, 0.f}};

    for (int d0 = 0; d0 < D; d0 += 64) {
        // xr: 32 rows x 64 d
#pragma unroll
        for (int r = 0; r < 2; r++) {
            int idx = tid + r * 256;
            int row = idx >> 4;
            int kk  = (idx & 15) * 4;
            float4 v = *reinterpret_cast<const float4*>(
                &xr[(size_t)(i0 + row) * HD + h * D + d0 + kk]);
            s_xr[kk + 0][row] = v.x;
            s_xr[kk + 1][row] = v.y;
            s_xr[kk + 2][row] = v.z;
            s_xr[kk + 3][row] = v.w;
        }
        // xl: 64 rows x 64 d
#pragma unroll
        for (int r = 0; r < 4; r++) {
            int idx = tid + r * 256;
            int row = idx >> 4;
            int kk  = (idx & 15) * 4;
            float4 v = *reinterpret_cast<const float4*>(
                &xl[(size_t)(j0 + row) * HD + h * D + d0 + kk]);
            s_xl[kk + 0][row] = v.x;
            s_xl[kk + 1][row] = v.y;
            s_xl[kk + 2][row] = v.z;
            s_xl[kk + 3][row] = v.w;
        }
        __syncthreads();
#pragma unroll 8
        for (int kk = 0; kk < 64; kk++) {
            float attv = s_attf[d0 + kk];
            float2 xrP = *reinterpret_cast<const float2*>(&s_xr[kk][ty * 2]);
            float4 xlP = *reinterpret_cast<const float4*>(&s_xl[kk][tx * 4]);
            acc[0][0] = fmaf(attv, fabsf(xrP.x + xlP.x), acc[0][0]);
            acc[0][1] = fmaf(attv, fabsf(xrP.x + xlP.y), acc[0][1]);
            acc[0][2] = fmaf(attv, fabsf(xrP.x + xlP.z), acc[0][2]);
            acc[0][3] = fmaf(attv, fabsf(xrP.x + xlP.w), acc[0][3]);
            acc[1][0] = fmaf(attv, fabsf(xrP.y + xlP.x), acc[1][0]);
            acc[1][1] = fmaf(attv, fabsf(xrP.y + xlP.y), acc[1][1]);
            acc[1][2] = fmaf(attv, fabsf(xrP.y + xlP.z), acc[1][2]);
            acc[1][3] = fmaf(attv, fabsf(xrP.y + xlP.w), acc[1][3]);
        }
        __syncthreads();
    }

    float4 alv = *reinterpret_cast<const float4*>(&g_al[h * NN + j0 + tx * 4]);
#pragma unroll
    for (int ii = 0; ii < 2; ii++) {
        int i = i0 + ty * 2 + ii;
        int jb = j0 + tx * 4;
        float4 o;
        o.x = fmaf(0.6f, alv.x, acc[ii][0]);
        o.y = fmaf(0.6f, alv.y, acc[ii][1]);
        o.z = fmaf(0.6f, alv.z, acc[ii][2]);
        o.w = fmaf(0.6f, alv.w, acc[ii][3]);
        if (i - jb >= 0 && i - jb < 4) {
            if (i == jb + 0) o.x = -INFINITY;
            if (i == jb + 1) o.y = -INFINITY;
            if (i == jb + 2) o.z = -INFINITY;
            if (i == jb + 3) o.w = -INFINITY;
        }
        *reinterpret_cast<float4*>(&s_out[((size_t)h * NN + i) * NN + jb]) = o;
    }
}

// ---------------- softmax: warp per row, 8 rows per CTA ----------------
__global__ __launch_bounds__(256)
void gat_softmax(float* __restrict__ s) {
    const int row = blockIdx.x * 8 + (threadIdx.x >> 5);
    const int lane = threadIdx.x & 31;
    float* r = s + (size_t)row * NN;

    float4 v0 = *reinterpret_cast<const float4*>(&r[lane * 8]);
    float4 v1 = *reinterpret_cast<const float4*>(&r[lane * 8 + 4]);
    float m = fmaxf(fmaxf(fmaxf(v0.x, v0.y), fmaxf(v0.z, v0.w)),
                    fmaxf(fmaxf(v1.x, v1.y), fmaxf(v1.z, v1.w)));
#pragma unroll
    for (int o = 16; o; o >>= 1) m = fmaxf(m, __shfl_xor_sync(0xffffffffu, m, o));
    v0.x = expf(v0.x - m); v0.y = expf(v0.y - m);
    v0.z = expf(v0.z - m); v0.w = expf(v0.w - m);
    v1.x = expf(v1.x - m); v1.y = expf(v1.y - m);
    v1.z = expf(v1.z - m); v1.w = expf(v1.w - m);
    float ss = v0.x + v0.y + v0.z + v0.w + v1.x + v1.y + v1.z + v1.w;
#pragma unroll
    for (int o = 16; o; o >>= 1) ss += __shfl_xor_sync(0xffffffffu, ss, o);
    float inv = 1.f / ss;
    v0.x *= inv; v0.y *= inv; v0.z *= inv; v0.w *= inv;
    v1.x *= inv; v1.y *= inv; v1.z *= inv; v1.w *= inv;
    *reinterpret_cast<float4*>(&r[lane * 8])     = v0;
    *reinterpret_cast<float4*>(&r[lane * 8 + 4]) = v1;
}

// ------- aggregation GEMM per head: out[i, h*D+n] = sum_j a[h,i,j]*xl[j,h*D+n] ----
template <int D, int ACT>
__global__ __launch_bounds__(256)
void gat_agg(const float* __restrict__ a, const float* __restrict__ xl,
             const float* __restrict__ bias, float* __restrict__ out) {
    const int HD = NH * D;
    const int h = blockIdx.z;
    const int brow = blockIdx.y * 32;
    const int bcol = blockIdx.x * 64;
    const float* A = a + (size_t)h * NN * NN;
    const float* B = xl + h * D;

    __shared__ __align__(16) float As[2][32][36];
    __shared__ __align__(16) float Ws[2][32][64];

    const int tid = threadIdx.x;
    const int tx = tid & 15, ty = tid >> 4;

    const int aIdx = tid * 4;
    const int am = aIdx >> 5, ak = aIdx & 31;
    const int wIdx0 = tid * 4, wIdx1 = wIdx0 + 1024;
    const int wk0 = wIdx0 >> 6, wn0 = wIdx0 & 63;
    const int wk1 = wIdx1 >> 6, wn1 = wIdx1 & 63;

    const float* Ap  = A + (size_t)(brow + am) * NN + ak;
    const float* Bp0 = B + (size_t)wk0 * HD + bcol + wn0;
    const float* Bp1 = B + (size_t)wk1 * HD + bcol + wn1;

    unsigned long long accP[2][2];
    accP[0][0] = accP[0][1] = accP[1][0] = accP[1][1] = 0ull;

    {
        float4 ra  = *reinterpret_cast<const float4*>(Ap);
        float4 rw0 = *reinterpret_cast<const float4*>(Bp0);
        float4 rw1 = *reinterpret_cast<const float4*>(Bp1);
        As[0][ak + 0][am] = ra.x;
        As[0][ak + 1][am] = ra.y;
        As[0][ak + 2][am] = ra.z;
        As[0][ak + 3][am] = ra.w;
        *reinterpret_cast<float4*>(&Ws[0][wk0][wn0]) = rw0;
        *reinterpret_cast<float4*>(&Ws[0][wk1][wn1]) = rw1;
    }
    __syncthreads();

    int buf = 0;
    const int nIters = NN / 32;
    for (int it = 0; it < nIters; it++) {
        const bool has_next = (it + 1) < nIters;
        float4 ra, rw0, rw1;
        if (has_next) {
            const int ko = (it + 1) * 32;
            ra  = *reinterpret_cast<const float4*>(Ap + ko);
            rw0 = *reinterpret_cast<const float4*>(Bp0 + (size_t)ko * HD);
            rw1 = *reinterpret_cast<const float4*>(Bp1 + (size_t)ko * HD);
        }
#pragma unroll
        for (int kk = 0; kk < 32; kk++) {
            float2 av = *reinterpret_cast<const float2*>(&As[buf][kk][ty * 2]);
            ulonglong2 wP = *reinterpret_cast<const ulonglong2*>(&Ws[buf][kk][tx * 4]);
            unsigned long long a0 = dupf(av.x);
            unsigned long long a1 = dupf(av.y);
            fma2(accP[0][0], a0, wP.x); fma2(accP[0][1], a0, wP.y);
            fma2(accP[1][0], a1, wP.x); fma2(accP[1][1], a1, wP.y);
        }
        if (has_next) {
            int nb = buf ^ 1;
            As[nb][ak + 0][am] = ra.x;
            As[nb][ak + 1][am] = ra.y;
            As[nb][ak + 2][am] = ra.z;
            As[nb][ak + 3][am] = ra.w;
            *reinterpret_cast<float4*>(&Ws[nb][wk0][wn0]) = rw0;
            *reinterpret_cast<float4*>(&Ws[nb][wk1][wn1]) = rw1;
            __syncthreads();
            buf = nb;
        }
    }

    const int n = bcol + tx * 4;
    float4 bv = *reinterpret_cast<const float4*>(&bias[h * D + n]);
#pragma unroll
    for (int i = 0; i < 2; i++) {
        int m = brow + ty * 2 + i;
        float2 lo = unpk(accP[i][0]);
        float2 hi = unpk(accP[i][1]);
        float4 o;
        o.x = lo.x + bv.x;
        o.y = lo.y + bv.y;
        o.z = hi.x + bv.z;
        o.w = hi.y + bv.w;
        if (ACT == 1) {
            o.x = o.x > 0.f ? o.x : expm1f(o.x);
            o.y = o.y > 0.f ? o.y : expm1f(o.y);
            o.z = o.z > 0.f ? o.z : expm1f(o.z);
            o.w = o.w > 0.f ? o.w : expm1f(o.w);
        }
        *reinterpret_cast<float4*>(&out[(size_t)m * HD + h * D + n]) = o;
    }
}

// ------- LayerNorm + ReLU + residual, rows 0..127; sums Wout's 16 split-K partials
__global__ __launch_bounds__(256)
void ln_residual(const float* __restrict__ bout,
                 const float* __restrict__ ln_g, const float* __restrict__ ln_b,
                 const float* __restrict__ rw,
                 const float* __restrict__ v1f, const float* __restrict__ v2f,
                 float* __restrict__ out) {
    const int i = blockIdx.x;
    const int tid = threadIdx.x;
    const int lane = tid & 31, warp = tid >> 5;
    const int MN = 128 * FDIM;
    __shared__ float s_red1[8], s_red2[8];
    __shared__ float s_mu, s_rstd;

    const float* res = (i < 64) ? (v1f + (size_t)i * FDIM)
                                : (v2f + (size_t)(i - 64) * FDIM);

    float yv[4];
    float sum = 0.f, sq = 0.f;
#pragma unroll
    for (int q = 0; q < 4; q++) {
        int c = tid + q * 256;
        float v = bout[c];
#pragma unroll
        for (int s = 0; s < 16; s++)
            v += g_part[(size_t)s * MN + i * FDIM + c];
        yv[q] = v;
        sum += v; sq += v * v;
    }
#pragma unroll
    for (int o = 16; o; o >>= 1) {
        sum += __shfl_xor_sync(0xffffffffu, sum, o);
        sq  += __shfl_xor_sync(0xffffffffu, sq,  o);
    }
    if (lane == 0) { s_red1[warp] = sum; s_red2[warp] = sq; }
    __syncthreads();
    if (tid == 0) {
        float ts = 0.f, tq = 0.f;
        for (int w = 0; w < 8; w++) { ts += s_red1[w]; tq += s_red2[w]; }
        float mu = ts / FDIM;
        float var = tq / FDIM - mu * mu;
        s_mu = mu;
        s_rstd = rsqrtf(var + 1e-5f);
    }
    __syncthreads();
    float mu = s_mu, rstd = s_rstd, w0 = rw[0];
#pragma unroll
    for (int q = 0; q < 4; q++) {
        int c = tid + q * 256;
        float v = (yv[q] - mu) * rstd * ln_g[c] + ln_b[c];
        v = fmaxf(v, 0.f);
        out[i * FDIM + c] = v + w0 * res[c];
    }
}

// ---------------- launch ----------------
extern "C" void kernel_launch(void* const* d_in, const int* in_sizes, int n_in,
                              void* d_out, int out_size) {
    (void)in_sizes; (void)n_in; (void)out_size;
    const float* v1f   = (const float*)d_in[0];
    const float* v2f   = (const float*)d_in[1];
    const float* v1fu  = (const float*)d_in[2];
    const float* v2fu  = (const float*)d_in[3];
    const float* Wl1   = (const float*)d_in[4];
    const float* bl1   = (const float*)d_in[5];
    const float* Wr1   = (const float*)d_in[6];
    const float* br1   = (const float*)d_in[7];
    const float* att1  = (const float*)d_in[8];
    const float* bias1 = (const float*)d_in[9];
    const float* Wl2   = (const float*)d_in[10];
    const float* bl2   = (const float*)d_in[11];
    const float* Wr2   = (const float*)d_in[12];
    const float* br2   = (const float*)d_in[13];
    const float* att2  = (const float*)d_in[14];
    const float* bias2 = (const float*)d_in[15];
    const float* Wout  = (const float*)d_in[16];
    const float* bout  = (const float*)d_in[17];
    const float* ln_g  = (const float*)d_in[18];
    const float* ln_b  = (const float*)d_in[19];
    const float* rw    = (const float*)d_in[20];
    float* out = (float*)d_out;

    float *xl1, *xr1, *o1, *xl2, *xr2, *o2, *sbuf;
    cudaGetSymbolAddress((void**)&xl1, g_xl1);
    cudaGetSymbolAddress((void**)&xr1, g_xr1);
    cudaGetSymbolAddress((void**)&o1,  g_o1);
    cudaGetSymbolAddress((void**)&xl2, g_xl2);
    cudaGetSymbolAddress((void**)&xr2, g_xr2);
    cudaGetSymbolAddress((void**)&o2,  g_o2);
    cudaGetSymbolAddress((void**)&sbuf, g_s);

    // ---- GAT layer 1 linear (reads the 4 inputs directly): split-K=2 -> 256 CTAs
    {
        dim3 grid(HD1 / 64, NN / 128, 4);
        gemm_pipe<<<grid, 256>>>(nullptr, v1f, v2f, v1fu, v2fu, Wl1, Wr1,
                                 NN, FDIM, HD1, 2, 1);
    }
    reduce_al1<<<NN, 256>>>(bl1, br1, att1);

    // ---- GAT layer 1 attention
    {
        dim3 grid(NN / 64, NN / 32, NH);
        gat_scores<HIDD><<<grid, 256>>>(xl1, xr1, att1, sbuf);
    }
    gat_softmax<<<NH * NN / 8, 256>>>(sbuf);
    {
        dim3 grid(HIDD / 64, NN / 32, NH);
        gat_agg<HIDD, 1><<<grid, 256>>>(sbuf, xl1, bias1, o1);
    }

    // ---- GAT layer 2 linear: split-K=4 -> 256 CTAs
    {
        dim3 grid(HD2 / 64, NN / 128, 8);
        gemm_pipe<<<grid, 256>>>(o1, nullptr, nullptr, nullptr, nullptr, Wl2, Wr2,
                                 NN, HD1, HD2, 4, 0);
    }
    reduce_al2<<<NN, 256>>>(bl2, br2, att2);

    // ---- GAT layer 2 attention
    {
        dim3 grid(NN / 64, NN / 32, NH);
        gat_scores<DD2><<<grid, 256>>>(xl2, xr2, att2, sbuf);
    }
    gat_softmax<<<NH * NN / 8, 256>>>(sbuf);
    {
        dim3 grid(DD2 / 64, NN / 32, NH);
        gat_agg<DD2, 0><<<grid, 256>>>(sbuf, xl2, bias2, o2);
    }

    // ---- Output projection rows 0..127: split-K=16 -> 256 CTAs
    {
        dim3 grid(FDIM / 64, 1, 16);
        gemm_pipe<<<grid, 256>>>(o2, nullptr, nullptr, nullptr, nullptr, Wout, Wout,
                                 128, FDIM, FDIM, 16, 0);
    }
    ln_residual<<<128, 256>>>(bout, ln_g, ln_b, rw, v1f, v2f, out);
}